// round 1
// baseline (speedup 1.0000x reference)
#include <cuda_runtime.h>
#include <math.h>

// Problem constants
#define BATCH 2
#define SEQ 2048
#define DMODEL 1024
#define NHEADS 16
#define HDIM 64
#define BH (BATCH*NHEADS)          // 32
#define MROWS (BATCH*SEQ)          // 4096

// Scratch (static device arrays -- no allocation allowed)
__device__ float g_Q[BH * SEQ * HDIM];   // [b*H+h][s][d]
__device__ float g_K[BH * SEQ * HDIM];
__device__ float g_V[BH * SEQ * HDIM];
__device__ float g_C[BATCH * SEQ * DMODEL]; // context in [B,S,D]

// ---------------------------------------------------------------------------
// GEMM: out[m,n] = sum_k A[m,k] * W[n,k] + bias[n]
// A: [M,K] row-major, W: [N,K] row-major. M=4096, N=1024, K=1024.
// head_layout=1 -> scatter into [B,H,S,hd]; else row-major [M,N].
// ---------------------------------------------------------------------------
#define GBM 64
#define GBN 64
#define GBK 32
#define GPAD 4
#define GSTRIDE (GBM + GPAD)   // 68

__global__ __launch_bounds__(256) void gemm_wt_kernel(
    const float* __restrict__ A,
    const float* __restrict__ W,
    const float* __restrict__ bias,
    float* __restrict__ out,
    int head_layout)
{
    __shared__ float As[GBK * GSTRIDE];  // [k][row]
    __shared__ float Ws[GBK * GSTRIDE];  // [k][col]

    const int tid = threadIdx.x;
    const int tx = tid & 15;
    const int ty = tid >> 4;
    const int row0 = blockIdx.y * GBM;
    const int col0 = blockIdx.x * GBN;

    float acc[4][4];
#pragma unroll
    for (int i = 0; i < 4; i++)
#pragma unroll
        for (int j = 0; j < 4; j++) acc[i][j] = 0.f;

    const int lr = tid >> 3;            // 0..31
    const int lc = (tid & 7) * 4;       // 0..28

    for (int k0 = 0; k0 < DMODEL; k0 += GBK) {
#pragma unroll
        for (int half = 0; half < 2; half++) {
            int rr = lr + half * 32;
            float4 a = *(const float4*)&A[(size_t)(row0 + rr) * DMODEL + k0 + lc];
            As[(lc + 0) * GSTRIDE + rr] = a.x;
            As[(lc + 1) * GSTRIDE + rr] = a.y;
            As[(lc + 2) * GSTRIDE + rr] = a.z;
            As[(lc + 3) * GSTRIDE + rr] = a.w;
            float4 w = *(const float4*)&W[(size_t)(col0 + rr) * DMODEL + k0 + lc];
            Ws[(lc + 0) * GSTRIDE + rr] = w.x;
            Ws[(lc + 1) * GSTRIDE + rr] = w.y;
            Ws[(lc + 2) * GSTRIDE + rr] = w.z;
            Ws[(lc + 3) * GSTRIDE + rr] = w.w;
        }
        __syncthreads();

#pragma unroll
        for (int kk = 0; kk < GBK; kk++) {
            float4 av = *(const float4*)&As[kk * GSTRIDE + ty * 4];
            float4 bv = *(const float4*)&Ws[kk * GSTRIDE + tx * 4];
            float a[4] = {av.x, av.y, av.z, av.w};
            float b[4] = {bv.x, bv.y, bv.z, bv.w};
#pragma unroll
            for (int i = 0; i < 4; i++)
#pragma unroll
                for (int j = 0; j < 4; j++)
                    acc[i][j] = fmaf(a[i], b[j], acc[i][j]);
        }
        __syncthreads();
    }

    // epilogue
#pragma unroll
    for (int i = 0; i < 4; i++) {
        int m = row0 + ty * 4 + i;
#pragma unroll
        for (int j = 0; j < 4; j++) {
            int n = col0 + tx * 4 + j;
            float v = acc[i][j] + bias[n];
            if (head_layout) {
                int b = m >> 11;          // m / SEQ
                int s = m & (SEQ - 1);
                int h = n >> 6;           // n / HDIM
                int d = n & (HDIM - 1);
                out[(((size_t)(b * NHEADS + h)) * SEQ + s) * HDIM + d] = v;
            } else {
                out[(size_t)m * DMODEL + n] = v;
            }
        }
    }
}

// ---------------------------------------------------------------------------
// RoPE applied in place to Q and K, layout [BH][S][hd]
// ---------------------------------------------------------------------------
__global__ __launch_bounds__(256) void rope_kernel(float* __restrict__ Q,
                                                   float* __restrict__ K)
{
    int idx = blockIdx.x * blockDim.x + threadIdx.x;  // over BH*S*32 pairs
    if (idx >= BH * SEQ * (HDIM / 2)) return;
    int pair = idx & 31;
    int s = (idx >> 5) & (SEQ - 1);
    int bh = idx >> 16;

    float inv_freq = powf(10000.0f, -(float)(2 * pair) / 64.0f);
    float ang = (float)s * inv_freq;
    float c = cosf(ang), sn = sinf(ang);

    size_t base = (((size_t)bh * SEQ) + s) * HDIM + 2 * pair;
    float2 q = *(float2*)&Q[base];
    float2 k = *(float2*)&K[base];
    float2 qo, ko;
    qo.x = q.x * c - q.y * sn;
    qo.y = q.x * sn + q.y * c;
    ko.x = k.x * c - k.y * sn;
    ko.y = k.x * sn + k.y * c;
    *(float2*)&Q[base] = qo;
    *(float2*)&K[base] = ko;
}

// ---------------------------------------------------------------------------
// Flash attention (causal). One CTA per (bh, 64-row q tile). 256 threads.
// Dynamic smem: Qs[64][68] (d-major), Ks[64][68] (d-major), Vs[64][68] (k-major),
// Ps[64][65] (k-major, transposed P).
// ---------------------------------------------------------------------------
#define APAD_STRIDE 68
#define PSTRIDE 65
#define ATT_SMEM_FLOATS (3 * 64 * APAD_STRIDE + 64 * PSTRIDE)
#define ATT_SMEM_BYTES (ATT_SMEM_FLOATS * 4)

__global__ __launch_bounds__(256) void attn_kernel(
    const float* __restrict__ Q,
    const float* __restrict__ K,
    const float* __restrict__ V,
    float* __restrict__ C)
{
    extern __shared__ float sm[];
    float* Qs = sm;                          // [d*68 + row]
    float* Ks = sm + 64 * APAD_STRIDE;       // [d*68 + col]
    float* Vs = sm + 2 * 64 * APAD_STRIDE;   // [k*68 + hd]
    float* Ps = sm + 3 * 64 * APAD_STRIDE;   // [k*65 + qrow]

    const int bh = blockIdx.y;
    const int qt = blockIdx.x;
    const int q0 = qt * 64;
    const int tid = threadIdx.x;
    const int tx = tid & 15;
    const int ty = tid >> 4;

    const float scale = 0.125f;  // 1/sqrt(64)
    const float* Qb = Q + (((size_t)bh * SEQ) + q0) * HDIM;

    {
        int r = tid >> 2;
        int c0 = (tid & 3) * 16;
#pragma unroll
        for (int t = 0; t < 4; t++) {
            int c = c0 + t * 4;
            float4 v = *(const float4*)&Qb[r * HDIM + c];
            Qs[(c + 0) * APAD_STRIDE + r] = v.x * scale;
            Qs[(c + 1) * APAD_STRIDE + r] = v.y * scale;
            Qs[(c + 2) * APAD_STRIDE + r] = v.z * scale;
            Qs[(c + 3) * APAD_STRIDE + r] = v.w * scale;
        }
    }

    float m_i[4], l_i[4], o[4][4];
#pragma unroll
    for (int i = 0; i < 4; i++) {
        m_i[i] = -INFINITY;
        l_i[i] = 0.f;
#pragma unroll
        for (int j = 0; j < 4; j++) o[i][j] = 0.f;
    }
    __syncthreads();

    for (int kt = 0; kt <= qt; kt++) {
        const int k0 = kt * 64;
        const float* Kb = K + (((size_t)bh * SEQ) + k0) * HDIM;
        const float* Vb = V + (((size_t)bh * SEQ) + k0) * HDIM;
        {
            int r = tid >> 2;
            int c0 = (tid & 3) * 16;
#pragma unroll
            for (int t = 0; t < 4; t++) {
                int c = c0 + t * 4;
                float4 kv = *(const float4*)&Kb[r * HDIM + c];
                Ks[(c + 0) * APAD_STRIDE + r] = kv.x;
                Ks[(c + 1) * APAD_STRIDE + r] = kv.y;
                Ks[(c + 2) * APAD_STRIDE + r] = kv.z;
                Ks[(c + 3) * APAD_STRIDE + r] = kv.w;
                float4 vv = *(const float4*)&Vb[r * HDIM + c];
                *(float4*)&Vs[r * APAD_STRIDE + c] = vv;
            }
        }
        __syncthreads();

        // S = Q @ K^T (scaled)
        float s[4][4];
#pragma unroll
        for (int i = 0; i < 4; i++)
#pragma unroll
            for (int j = 0; j < 4; j++) s[i][j] = 0.f;

#pragma unroll 16
        for (int d = 0; d < 64; d++) {
            float4 av = *(const float4*)&Qs[d * APAD_STRIDE + ty * 4];
            float4 bv = *(const float4*)&Ks[d * APAD_STRIDE + tx * 4];
            float a[4] = {av.x, av.y, av.z, av.w};
            float b[4] = {bv.x, bv.y, bv.z, bv.w};
#pragma unroll
            for (int i = 0; i < 4; i++)
#pragma unroll
                for (int j = 0; j < 4; j++)
                    s[i][j] = fmaf(a[i], b[j], s[i][j]);
        }

        // causal mask on the diagonal tile
        if (kt == qt) {
#pragma unroll
            for (int i = 0; i < 4; i++) {
                int qr = ty * 4 + i;
#pragma unroll
                for (int j = 0; j < 4; j++) {
                    if (tx * 4 + j > qr) s[i][j] = -INFINITY;
                }
            }
        }

        // online softmax
#pragma unroll
        for (int i = 0; i < 4; i++) {
            float mt = fmaxf(fmaxf(s[i][0], s[i][1]), fmaxf(s[i][2], s[i][3]));
#pragma unroll
            for (int off = 8; off > 0; off >>= 1)
                mt = fmaxf(mt, __shfl_xor_sync(0xffffffffu, mt, off));
            float mn = fmaxf(m_i[i], mt);
            float corr = __expf(m_i[i] - mn);  // exp(-inf)=0 on first tile
            float lt = 0.f;
#pragma unroll
            for (int j = 0; j < 4; j++) {
                s[i][j] = __expf(s[i][j] - mn);
                lt += s[i][j];
            }
#pragma unroll
            for (int off = 8; off > 0; off >>= 1)
                lt += __shfl_xor_sync(0xffffffffu, lt, off);
            l_i[i] = l_i[i] * corr + lt;
            m_i[i] = mn;
#pragma unroll
            for (int j = 0; j < 4; j++) o[i][j] *= corr;
        }

        // store P transposed: Ps[kcol][qrow]
#pragma unroll
        for (int i = 0; i < 4; i++)
#pragma unroll
            for (int j = 0; j < 4; j++)
                Ps[(tx * 4 + j) * PSTRIDE + ty * 4 + i] = s[i][j];
        __syncthreads();

        // O += P @ V
#pragma unroll 16
        for (int k = 0; k < 64; k++) {
            float4 bv = *(const float4*)&Vs[k * APAD_STRIDE + tx * 4];
            float b[4] = {bv.x, bv.y, bv.z, bv.w};
            float a[4];
#pragma unroll
            for (int i = 0; i < 4; i++) a[i] = Ps[k * PSTRIDE + ty * 4 + i];
#pragma unroll
            for (int i = 0; i < 4; i++)
#pragma unroll
                for (int j = 0; j < 4; j++)
                    o[i][j] = fmaf(a[i], b[j], o[i][j]);
        }
        __syncthreads();
    }

    // write context [B,S,D]
    const int b = bh >> 4;
    const int h = bh & 15;
#pragma unroll
    for (int i = 0; i < 4; i++) {
        float inv = 1.0f / l_i[i];
        int srow = q0 + ty * 4 + i;
        float4 w = make_float4(o[i][0] * inv, o[i][1] * inv, o[i][2] * inv,
                               o[i][3] * inv);
        *(float4*)&C[((size_t)b * SEQ + srow) * DMODEL + h * HDIM + tx * 4] = w;
    }
}

// ---------------------------------------------------------------------------
// Launch
// ---------------------------------------------------------------------------
extern "C" void kernel_launch(void* const* d_in, const int* in_sizes, int n_in,
                              void* d_out, int out_size)
{
    const float* x  = (const float*)d_in[0];
    const float* Wq = (const float*)d_in[1];
    const float* bq = (const float*)d_in[2];
    const float* Wk = (const float*)d_in[3];
    const float* bk = (const float*)d_in[4];
    const float* Wv = (const float*)d_in[5];
    const float* bv = (const float*)d_in[6];
    const float* Wo = (const float*)d_in[7];
    const float* bo = (const float*)d_in[8];
    float* out = (float*)d_out;

    float *Q, *K, *V, *C;
    cudaGetSymbolAddress((void**)&Q, g_Q);
    cudaGetSymbolAddress((void**)&K, g_K);
    cudaGetSymbolAddress((void**)&V, g_V);
    cudaGetSymbolAddress((void**)&C, g_C);

    static int smem_set = 0;
    if (!smem_set) {
        cudaFuncSetAttribute(attn_kernel,
                             cudaFuncAttributeMaxDynamicSharedMemorySize,
                             ATT_SMEM_BYTES);
        smem_set = 1;
    }

    dim3 ggrid(DMODEL / GBN, MROWS / GBM);  // (16, 64)
    gemm_wt_kernel<<<ggrid, 256>>>(x, Wq, bq, Q, 1);
    gemm_wt_kernel<<<ggrid, 256>>>(x, Wk, bk, K, 1);
    gemm_wt_kernel<<<ggrid, 256>>>(x, Wv, bv, V, 1);

    int rope_threads = BH * SEQ * (HDIM / 2);
    rope_kernel<<<(rope_threads + 255) / 256, 256>>>(Q, K);

    dim3 agrid(SEQ / 64, BH);  // (32, 32)
    attn_kernel<<<agrid, 256, ATT_SMEM_BYTES>>>(Q, K, V, C);

    gemm_wt_kernel<<<ggrid, 256>>>(C, Wo, bo, out, 0);
}

// round 3
// speedup vs baseline: 1.5930x; 1.5930x over previous
#include <cuda_runtime.h>
#include <math.h>
#include <cstdint>

// Problem constants
#define BATCH 2
#define SEQ 2048
#define DMODEL 1024
#define NHEADS 16
#define HDIM 64
#define BH (BATCH*NHEADS)          // 32
#define MROWS (BATCH*SEQ)          // 4096

// Scratch (static device arrays -- no allocation allowed)
__device__ float g_Q[BH * SEQ * HDIM];   // [b*H+h][s][d]
__device__ float g_K[BH * SEQ * HDIM];
__device__ float g_V[BH * SEQ * HDIM];
__device__ float g_C[BATCH * SEQ * DMODEL]; // context in [B,S,D]

// ===========================================================================
// Helpers
// ===========================================================================
__device__ __forceinline__ uint32_t f2tf32(float x) {
    uint32_t r;
    asm("cvt.rna.tf32.f32 %0, %1;" : "=r"(r) : "f"(x));
    return r;
}

__device__ __forceinline__ void mma_tf32(float& d0, float& d1, float& d2, float& d3,
                                         uint32_t a0, uint32_t a1, uint32_t a2, uint32_t a3,
                                         uint32_t b0, uint32_t b1) {
    asm volatile(
        "mma.sync.aligned.m16n8k8.row.col.f32.tf32.tf32.f32 "
        "{%0,%1,%2,%3}, {%4,%5,%6,%7}, {%8,%9}, {%0,%1,%2,%3};"
        : "+f"(d0), "+f"(d1), "+f"(d2), "+f"(d3)
        : "r"(a0), "r"(a1), "r"(a2), "r"(a3), "r"(b0), "r"(b1));
}

__device__ __forceinline__ void cp_async16(uint32_t smem_addr, const void* gmem) {
    asm volatile("cp.async.cg.shared.global [%0], [%1], 16;"
                 :: "r"(smem_addr), "l"(gmem) : "memory");
}
#define CP_ASYNC_COMMIT() asm volatile("cp.async.commit_group;" ::: "memory")

__device__ __forceinline__ uint32_t smem_u32(const void* p) {
    uint32_t a;
    asm("{ .reg .u64 t; cvta.to.shared.u64 t, %1; cvt.u32.u64 %0, t; }"
        : "=r"(a) : "l"(p));
    return a;
}

// ===========================================================================
// tf32 mma.sync GEMM: out[m,n] = sum_k A[m,k] * W[n,k] + bias[n]
// A: [4096,1024] row-major, W: [1024,1024] row-major (so W is "col-major B").
// CTA tile 128x128, BK=32, 256 threads = 8 warps (2 over M x 4 over N),
// warp tile 64x32 = 4x4 atoms of m16n8k8.
// ===========================================================================
#define TBM 128
#define TBN 128
#define TBK 32
#define NCH (DMODEL / TBK)      // 32
#define SSTRIDE 36              // floats per smem row (pad 32 -> 36)
#define STAGE_FLOATS (TBM * SSTRIDE)       // 4608 floats = 18432 B
#define SM_TOTAL (4 * STAGE_FLOATS * 4)    // A0,B0,A1,B1 = 73728 B

__global__ __launch_bounds__(256)
void gemm_tc(const float* __restrict__ A,
             const float* __restrict__ W,
             const float* __restrict__ bias,
             float* __restrict__ out,
             int head_layout)
{
    extern __shared__ __align__(16) float sm[];
    float* As[2] = {sm, sm + 2 * STAGE_FLOATS};
    float* Bs[2] = {sm + STAGE_FLOATS, sm + 3 * STAGE_FLOATS};

    const int tid = threadIdx.x;
    const int wid = tid >> 5;
    const int lane = tid & 31;
    const int wm = wid & 1;       // 0..1 (64-row halves)
    const int wn = wid >> 1;      // 0..3 (32-col quarters)
    const int g = lane >> 2;      // 0..7
    const int t = lane & 3;       // 0..3

    const int row0 = blockIdx.y * TBM;
    const int col0 = blockIdx.x * TBN;

    // loader mapping: row = tid>>3 (0..31), chunk = tid&7 (16B units)
    const int lrow = tid >> 3;
    const int lch = tid & 7;

    float acc[4][4][4];
#pragma unroll
    for (int i = 0; i < 4; i++)
#pragma unroll
        for (int j = 0; j < 4; j++)
#pragma unroll
            for (int r = 0; r < 4; r++) acc[i][j][r] = 0.f;

    // prefetch chunk 0
    {
        const int k0 = 0;
        uint32_t abase = smem_u32(As[0]);
        uint32_t bbase = smem_u32(Bs[0]);
#pragma unroll
        for (int i = 0; i < 4; i++) {
            int r = lrow + i * 32;
            uint32_t off = (uint32_t)(r * SSTRIDE * 4 + lch * 16);
            cp_async16(abase + off, &A[(size_t)(row0 + r) * DMODEL + k0 + lch * 4]);
            cp_async16(bbase + off, &W[(size_t)(col0 + r) * DMODEL + k0 + lch * 4]);
        }
        CP_ASYNC_COMMIT();
    }

    for (int c = 0; c < NCH; c++) {
        if (c + 1 < NCH) {
            const int k0 = (c + 1) * TBK;
            const int buf = (c + 1) & 1;
            uint32_t abase = smem_u32(As[buf]);
            uint32_t bbase = smem_u32(Bs[buf]);
#pragma unroll
            for (int i = 0; i < 4; i++) {
                int r = lrow + i * 32;
                uint32_t off = (uint32_t)(r * SSTRIDE * 4 + lch * 16);
                cp_async16(abase + off, &A[(size_t)(row0 + r) * DMODEL + k0 + lch * 4]);
                cp_async16(bbase + off, &W[(size_t)(col0 + r) * DMODEL + k0 + lch * 4]);
            }
            CP_ASYNC_COMMIT();
            asm volatile("cp.async.wait_group 1;" ::: "memory");
        } else {
            asm volatile("cp.async.wait_group 0;" ::: "memory");
        }
        __syncthreads();

        const float* Asb = As[c & 1];
        const float* Bsb = Bs[c & 1];
#pragma unroll
        for (int ks = 0; ks < 4; ks++) {
            const int k0 = ks * 8;
            uint32_t afr[4][4];
#pragma unroll
            for (int am = 0; am < 4; am++) {
                int r = wm * 64 + am * 16 + g;
                afr[am][0] = f2tf32(Asb[r * SSTRIDE + k0 + t]);
                afr[am][1] = f2tf32(Asb[(r + 8) * SSTRIDE + k0 + t]);
                afr[am][2] = f2tf32(Asb[r * SSTRIDE + k0 + t + 4]);
                afr[am][3] = f2tf32(Asb[(r + 8) * SSTRIDE + k0 + t + 4]);
            }
            uint32_t bfr[4][2];
#pragma unroll
            for (int bn = 0; bn < 4; bn++) {
                int n = wn * 32 + bn * 8 + g;
                bfr[bn][0] = f2tf32(Bsb[n * SSTRIDE + k0 + t]);
                bfr[bn][1] = f2tf32(Bsb[n * SSTRIDE + k0 + t + 4]);
            }
#pragma unroll
            for (int am = 0; am < 4; am++)
#pragma unroll
                for (int bn = 0; bn < 4; bn++)
                    mma_tf32(acc[am][bn][0], acc[am][bn][1],
                             acc[am][bn][2], acc[am][bn][3],
                             afr[am][0], afr[am][1], afr[am][2], afr[am][3],
                             bfr[bn][0], bfr[bn][1]);
        }
        __syncthreads();
    }

    // epilogue
#pragma unroll
    for (int bn = 0; bn < 4; bn++) {
        const int n0 = col0 + wn * 32 + bn * 8 + 2 * t;
        const float b0 = __ldg(&bias[n0]);
        const float b1 = __ldg(&bias[n0 + 1]);
#pragma unroll
        for (int am = 0; am < 4; am++) {
            const int r0 = row0 + wm * 64 + am * 16 + g;
            float2 v0 = make_float2(acc[am][bn][0] + b0, acc[am][bn][1] + b1);
            float2 v1 = make_float2(acc[am][bn][2] + b0, acc[am][bn][3] + b1);
            if (head_layout) {
                int h = n0 >> 6;
                int d = n0 & (HDIM - 1);
                {
                    int b = r0 >> 11, s = r0 & (SEQ - 1);
                    *(float2*)&out[(((size_t)(b * NHEADS + h)) * SEQ + s) * HDIM + d] = v0;
                }
                {
                    int m2 = r0 + 8;
                    int b = m2 >> 11, s = m2 & (SEQ - 1);
                    *(float2*)&out[(((size_t)(b * NHEADS + h)) * SEQ + s) * HDIM + d] = v1;
                }
            } else {
                *(float2*)&out[(size_t)r0 * DMODEL + n0] = v0;
                *(float2*)&out[(size_t)(r0 + 8) * DMODEL + n0] = v1;
            }
        }
    }
}

// ---------------------------------------------------------------------------
// RoPE applied in place to Q and K, layout [BH][S][hd]
// ---------------------------------------------------------------------------
__global__ __launch_bounds__(256) void rope_kernel(float* __restrict__ Q,
                                                   float* __restrict__ K)
{
    int idx = blockIdx.x * blockDim.x + threadIdx.x;
    if (idx >= BH * SEQ * (HDIM / 2)) return;
    int pair = idx & 31;
    int s = (idx >> 5) & (SEQ - 1);
    int bh = idx >> 16;

    float inv_freq = powf(10000.0f, -(float)(2 * pair) / 64.0f);
    float ang = (float)s * inv_freq;
    float c = cosf(ang), sn = sinf(ang);

    size_t base = (((size_t)bh * SEQ) + s) * HDIM + 2 * pair;
    float2 q = *(float2*)&Q[base];
    float2 k = *(float2*)&K[base];
    float2 qo, ko;
    qo.x = q.x * c - q.y * sn;
    qo.y = q.x * sn + q.y * c;
    ko.x = k.x * c - k.y * sn;
    ko.y = k.x * sn + k.y * c;
    *(float2*)&Q[base] = qo;
    *(float2*)&K[base] = ko;
}

// ---------------------------------------------------------------------------
// Flash attention (causal). One CTA per (bh, 64-row q tile). 256 threads.
// ---------------------------------------------------------------------------
#define APAD_STRIDE 68
#define PSTRIDE 65
#define ATT_SMEM_FLOATS (3 * 64 * APAD_STRIDE + 64 * PSTRIDE)
#define ATT_SMEM_BYTES (ATT_SMEM_FLOATS * 4)

__global__ __launch_bounds__(256) void attn_kernel(
    const float* __restrict__ Q,
    const float* __restrict__ K,
    const float* __restrict__ V,
    float* __restrict__ C)
{
    extern __shared__ float sm[];
    float* Qs = sm;
    float* Ks = sm + 64 * APAD_STRIDE;
    float* Vs = sm + 2 * 64 * APAD_STRIDE;
    float* Ps = sm + 3 * 64 * APAD_STRIDE;

    const int bh = blockIdx.y;
    const int qt = blockIdx.x;
    const int q0 = qt * 64;
    const int tid = threadIdx.x;
    const int tx = tid & 15;
    const int ty = tid >> 4;

    const float scale = 0.125f;
    const float* Qb = Q + (((size_t)bh * SEQ) + q0) * HDIM;

    {
        int r = tid >> 2;
        int c0 = (tid & 3) * 16;
#pragma unroll
        for (int tt = 0; tt < 4; tt++) {
            int c = c0 + tt * 4;
            float4 v = *(const float4*)&Qb[r * HDIM + c];
            Qs[(c + 0) * APAD_STRIDE + r] = v.x * scale;
            Qs[(c + 1) * APAD_STRIDE + r] = v.y * scale;
            Qs[(c + 2) * APAD_STRIDE + r] = v.z * scale;
            Qs[(c + 3) * APAD_STRIDE + r] = v.w * scale;
        }
    }

    float m_i[4], l_i[4], o[4][4];
#pragma unroll
    for (int i = 0; i < 4; i++) {
        m_i[i] = -INFINITY;
        l_i[i] = 0.f;
#pragma unroll
        for (int j = 0; j < 4; j++) o[i][j] = 0.f;
    }
    __syncthreads();

    for (int kt = 0; kt <= qt; kt++) {
        const int k0 = kt * 64;
        const float* Kb = K + (((size_t)bh * SEQ) + k0) * HDIM;
        const float* Vb = V + (((size_t)bh * SEQ) + k0) * HDIM;
        {
            int r = tid >> 2;
            int c0 = (tid & 3) * 16;
#pragma unroll
            for (int tt = 0; tt < 4; tt++) {
                int c = c0 + tt * 4;
                float4 kv = *(const float4*)&Kb[r * HDIM + c];
                Ks[(c + 0) * APAD_STRIDE + r] = kv.x;
                Ks[(c + 1) * APAD_STRIDE + r] = kv.y;
                Ks[(c + 2) * APAD_STRIDE + r] = kv.z;
                Ks[(c + 3) * APAD_STRIDE + r] = kv.w;
                float4 vv = *(const float4*)&Vb[r * HDIM + c];
                *(float4*)&Vs[r * APAD_STRIDE + c] = vv;
            }
        }
        __syncthreads();

        float s[4][4];
#pragma unroll
        for (int i = 0; i < 4; i++)
#pragma unroll
            for (int j = 0; j < 4; j++) s[i][j] = 0.f;

#pragma unroll 16
        for (int d = 0; d < 64; d++) {
            float4 av = *(const float4*)&Qs[d * APAD_STRIDE + ty * 4];
            float4 bv = *(const float4*)&Ks[d * APAD_STRIDE + tx * 4];
            float a[4] = {av.x, av.y, av.z, av.w};
            float b[4] = {bv.x, bv.y, bv.z, bv.w};
#pragma unroll
            for (int i = 0; i < 4; i++)
#pragma unroll
                for (int j = 0; j < 4; j++)
                    s[i][j] = fmaf(a[i], b[j], s[i][j]);
        }

        if (kt == qt) {
#pragma unroll
            for (int i = 0; i < 4; i++) {
                int qr = ty * 4 + i;
#pragma unroll
                for (int j = 0; j < 4; j++) {
                    if (tx * 4 + j > qr) s[i][j] = -INFINITY;
                }
            }
        }

#pragma unroll
        for (int i = 0; i < 4; i++) {
            float mt = fmaxf(fmaxf(s[i][0], s[i][1]), fmaxf(s[i][2], s[i][3]));
#pragma unroll
            for (int off = 8; off > 0; off >>= 1)
                mt = fmaxf(mt, __shfl_xor_sync(0xffffffffu, mt, off));
            float mn = fmaxf(m_i[i], mt);
            float corr = __expf(m_i[i] - mn);
            float lt = 0.f;
#pragma unroll
            for (int j = 0; j < 4; j++) {
                s[i][j] = __expf(s[i][j] - mn);
                lt += s[i][j];
            }
#pragma unroll
            for (int off = 8; off > 0; off >>= 1)
                lt += __shfl_xor_sync(0xffffffffu, lt, off);
            l_i[i] = l_i[i] * corr + lt;
            m_i[i] = mn;
#pragma unroll
            for (int j = 0; j < 4; j++) o[i][j] *= corr;
        }

#pragma unroll
        for (int i = 0; i < 4; i++)
#pragma unroll
            for (int j = 0; j < 4; j++)
                Ps[(tx * 4 + j) * PSTRIDE + ty * 4 + i] = s[i][j];
        __syncthreads();

#pragma unroll 16
        for (int k = 0; k < 64; k++) {
            float4 bv = *(const float4*)&Vs[k * APAD_STRIDE + tx * 4];
            float b[4] = {bv.x, bv.y, bv.z, bv.w};
            float a[4];
#pragma unroll
            for (int i = 0; i < 4; i++) a[i] = Ps[k * PSTRIDE + ty * 4 + i];
#pragma unroll
            for (int i = 0; i < 4; i++)
#pragma unroll
                for (int j = 0; j < 4; j++)
                    o[i][j] = fmaf(a[i], b[j], o[i][j]);
        }
        __syncthreads();
    }

    const int b = bh >> 4;
    const int h = bh & 15;
#pragma unroll
    for (int i = 0; i < 4; i++) {
        float inv = 1.0f / l_i[i];
        int srow = q0 + ty * 4 + i;
        float4 w = make_float4(o[i][0] * inv, o[i][1] * inv, o[i][2] * inv,
                               o[i][3] * inv);
        *(float4*)&C[((size_t)b * SEQ + srow) * DMODEL + h * HDIM + tx * 4] = w;
    }
}

// ---------------------------------------------------------------------------
// Launch
// ---------------------------------------------------------------------------
extern "C" void kernel_launch(void* const* d_in, const int* in_sizes, int n_in,
                              void* d_out, int out_size)
{
    const float* x  = (const float*)d_in[0];
    const float* Wq = (const float*)d_in[1];
    const float* bq = (const float*)d_in[2];
    const float* Wk = (const float*)d_in[3];
    const float* bk = (const float*)d_in[4];
    const float* Wv = (const float*)d_in[5];
    const float* bv = (const float*)d_in[6];
    const float* Wo = (const float*)d_in[7];
    const float* bo = (const float*)d_in[8];
    float* out = (float*)d_out;

    float *Q, *K, *V, *C;
    cudaGetSymbolAddress((void**)&Q, g_Q);
    cudaGetSymbolAddress((void**)&K, g_K);
    cudaGetSymbolAddress((void**)&V, g_V);
    cudaGetSymbolAddress((void**)&C, g_C);

    static int attr_set = 0;
    if (!attr_set) {
        cudaFuncSetAttribute(attn_kernel,
                             cudaFuncAttributeMaxDynamicSharedMemorySize,
                             ATT_SMEM_BYTES);
        cudaFuncSetAttribute(gemm_tc,
                             cudaFuncAttributeMaxDynamicSharedMemorySize,
                             SM_TOTAL);
        attr_set = 1;
    }

    dim3 ggrid(DMODEL / TBN, MROWS / TBM);  // (8, 32)
    gemm_tc<<<ggrid, 256, SM_TOTAL>>>(x, Wq, bq, Q, 1);
    gemm_tc<<<ggrid, 256, SM_TOTAL>>>(x, Wk, bk, K, 1);
    gemm_tc<<<ggrid, 256, SM_TOTAL>>>(x, Wv, bv, V, 1);

    int rope_threads = BH * SEQ * (HDIM / 2);
    rope_kernel<<<(rope_threads + 255) / 256, 256>>>(Q, K);

    dim3 agrid(SEQ / 64, BH);  // (32, 32)
    attn_kernel<<<agrid, 256, ATT_SMEM_BYTES>>>(Q, K, V, C);

    gemm_tc<<<ggrid, 256, SM_TOTAL>>>(C, Wo, bo, out, 0);
}

// round 4
// speedup vs baseline: 2.5910x; 1.6265x over previous
#include <cuda_runtime.h>
#include <math.h>
#include <cstdint>

// Problem constants
#define BATCH 2
#define SEQ 2048
#define DMODEL 1024
#define NHEADS 16
#define HDIM 64
#define BH (BATCH*NHEADS)          // 32
#define MROWS (BATCH*SEQ)          // 4096

// Scratch (static device arrays -- no allocation allowed)
__device__ float g_Q[BH * SEQ * HDIM];
__device__ float g_K[BH * SEQ * HDIM];
__device__ float g_V[BH * SEQ * HDIM];
__device__ float g_C[BATCH * SEQ * DMODEL];

// ===========================================================================
// Helpers
// ===========================================================================
__device__ __forceinline__ uint32_t f2tf32(float x) {
    uint32_t r;
    asm("cvt.rna.tf32.f32 %0, %1;" : "=r"(r) : "f"(x));
    return r;
}

__device__ __forceinline__ void mma_tf32(float& d0, float& d1, float& d2, float& d3,
                                         uint32_t a0, uint32_t a1, uint32_t a2, uint32_t a3,
                                         uint32_t b0, uint32_t b1) {
    asm volatile(
        "mma.sync.aligned.m16n8k8.row.col.f32.tf32.tf32.f32 "
        "{%0,%1,%2,%3}, {%4,%5,%6,%7}, {%8,%9}, {%0,%1,%2,%3};"
        : "+f"(d0), "+f"(d1), "+f"(d2), "+f"(d3)
        : "r"(a0), "r"(a1), "r"(a2), "r"(a3), "r"(b0), "r"(b1));
}

__device__ __forceinline__ void cp_async16(uint32_t smem_addr, const void* gmem) {
    asm volatile("cp.async.cg.shared.global [%0], [%1], 16;"
                 :: "r"(smem_addr), "l"(gmem) : "memory");
}
#define CP_ASYNC_COMMIT() asm volatile("cp.async.commit_group;" ::: "memory")

__device__ __forceinline__ uint32_t smem_u32(const void* p) {
    uint32_t a;
    asm("{ .reg .u64 t; cvta.to.shared.u64 t, %1; cvt.u32.u64 %0, t; }"
        : "=r"(a) : "l"(p));
    return a;
}

// ===========================================================================
// tf32 mma.sync GEMM (unchanged from round 3): out[m,n] = A[m,:]·W[n,:] + bias[n]
// ===========================================================================
#define TBM 128
#define TBN 128
#define TBK 32
#define NCH (DMODEL / TBK)
#define SSTRIDE 36
#define STAGE_FLOATS (TBM * SSTRIDE)
#define SM_TOTAL (4 * STAGE_FLOATS * 4)

__global__ __launch_bounds__(256)
void gemm_tc(const float* __restrict__ A,
             const float* __restrict__ W,
             const float* __restrict__ bias,
             float* __restrict__ out,
             int head_layout)
{
    extern __shared__ __align__(16) float sm[];
    float* As[2] = {sm, sm + 2 * STAGE_FLOATS};
    float* Bs[2] = {sm + STAGE_FLOATS, sm + 3 * STAGE_FLOATS};

    const int tid = threadIdx.x;
    const int wid = tid >> 5;
    const int lane = tid & 31;
    const int wm = wid & 1;
    const int wn = wid >> 1;
    const int g = lane >> 2;
    const int t = lane & 3;

    const int row0 = blockIdx.y * TBM;
    const int col0 = blockIdx.x * TBN;

    const int lrow = tid >> 3;
    const int lch = tid & 7;

    float acc[4][4][4];
#pragma unroll
    for (int i = 0; i < 4; i++)
#pragma unroll
        for (int j = 0; j < 4; j++)
#pragma unroll
            for (int r = 0; r < 4; r++) acc[i][j][r] = 0.f;

    {
        uint32_t abase = smem_u32(As[0]);
        uint32_t bbase = smem_u32(Bs[0]);
#pragma unroll
        for (int i = 0; i < 4; i++) {
            int r = lrow + i * 32;
            uint32_t off = (uint32_t)(r * SSTRIDE * 4 + lch * 16);
            cp_async16(abase + off, &A[(size_t)(row0 + r) * DMODEL + lch * 4]);
            cp_async16(bbase + off, &W[(size_t)(col0 + r) * DMODEL + lch * 4]);
        }
        CP_ASYNC_COMMIT();
    }

    for (int c = 0; c < NCH; c++) {
        if (c + 1 < NCH) {
            const int k0 = (c + 1) * TBK;
            const int buf = (c + 1) & 1;
            uint32_t abase = smem_u32(As[buf]);
            uint32_t bbase = smem_u32(Bs[buf]);
#pragma unroll
            for (int i = 0; i < 4; i++) {
                int r = lrow + i * 32;
                uint32_t off = (uint32_t)(r * SSTRIDE * 4 + lch * 16);
                cp_async16(abase + off, &A[(size_t)(row0 + r) * DMODEL + k0 + lch * 4]);
                cp_async16(bbase + off, &W[(size_t)(col0 + r) * DMODEL + k0 + lch * 4]);
            }
            CP_ASYNC_COMMIT();
            asm volatile("cp.async.wait_group 1;" ::: "memory");
        } else {
            asm volatile("cp.async.wait_group 0;" ::: "memory");
        }
        __syncthreads();

        const float* Asb = As[c & 1];
        const float* Bsb = Bs[c & 1];
#pragma unroll
        for (int ks = 0; ks < 4; ks++) {
            const int k0 = ks * 8;
            uint32_t afr[4][4];
#pragma unroll
            for (int am = 0; am < 4; am++) {
                int r = wm * 64 + am * 16 + g;
                afr[am][0] = f2tf32(Asb[r * SSTRIDE + k0 + t]);
                afr[am][1] = f2tf32(Asb[(r + 8) * SSTRIDE + k0 + t]);
                afr[am][2] = f2tf32(Asb[r * SSTRIDE + k0 + t + 4]);
                afr[am][3] = f2tf32(Asb[(r + 8) * SSTRIDE + k0 + t + 4]);
            }
            uint32_t bfr[4][2];
#pragma unroll
            for (int bn = 0; bn < 4; bn++) {
                int n = wn * 32 + bn * 8 + g;
                bfr[bn][0] = f2tf32(Bsb[n * SSTRIDE + k0 + t]);
                bfr[bn][1] = f2tf32(Bsb[n * SSTRIDE + k0 + t + 4]);
            }
#pragma unroll
            for (int am = 0; am < 4; am++)
#pragma unroll
                for (int bn = 0; bn < 4; bn++)
                    mma_tf32(acc[am][bn][0], acc[am][bn][1],
                             acc[am][bn][2], acc[am][bn][3],
                             afr[am][0], afr[am][1], afr[am][2], afr[am][3],
                             bfr[bn][0], bfr[bn][1]);
        }
        __syncthreads();
    }

#pragma unroll
    for (int bn = 0; bn < 4; bn++) {
        const int n0 = col0 + wn * 32 + bn * 8 + 2 * t;
        const float b0 = __ldg(&bias[n0]);
        const float b1 = __ldg(&bias[n0 + 1]);
#pragma unroll
        for (int am = 0; am < 4; am++) {
            const int r0 = row0 + wm * 64 + am * 16 + g;
            float2 v0 = make_float2(acc[am][bn][0] + b0, acc[am][bn][1] + b1);
            float2 v1 = make_float2(acc[am][bn][2] + b0, acc[am][bn][3] + b1);
            if (head_layout) {
                int h = n0 >> 6;
                int d = n0 & (HDIM - 1);
                {
                    int b = r0 >> 11, s = r0 & (SEQ - 1);
                    *(float2*)&out[(((size_t)(b * NHEADS + h)) * SEQ + s) * HDIM + d] = v0;
                }
                {
                    int m2 = r0 + 8;
                    int b = m2 >> 11, s = m2 & (SEQ - 1);
                    *(float2*)&out[(((size_t)(b * NHEADS + h)) * SEQ + s) * HDIM + d] = v1;
                }
            } else {
                *(float2*)&out[(size_t)r0 * DMODEL + n0] = v0;
                *(float2*)&out[(size_t)(r0 + 8) * DMODEL + n0] = v1;
            }
        }
    }
}

// ---------------------------------------------------------------------------
// RoPE (in place), layout [BH][S][hd]
// ---------------------------------------------------------------------------
__global__ __launch_bounds__(256) void rope_kernel(float* __restrict__ Q,
                                                   float* __restrict__ K)
{
    int idx = blockIdx.x * blockDim.x + threadIdx.x;
    if (idx >= BH * SEQ * (HDIM / 2)) return;
    int pair = idx & 31;
    int s = (idx >> 5) & (SEQ - 1);
    int bh = idx >> 16;

    float inv_freq = powf(10000.0f, -(float)(2 * pair) / 64.0f);
    float ang = (float)s * inv_freq;
    float c = cosf(ang), sn = sinf(ang);

    size_t base = (((size_t)bh * SEQ) + s) * HDIM + 2 * pair;
    float2 q = *(float2*)&Q[base];
    float2 k = *(float2*)&K[base];
    float2 qo, ko;
    qo.x = q.x * c - q.y * sn;
    qo.y = q.x * sn + q.y * c;
    ko.x = k.x * c - k.y * sn;
    ko.y = k.x * sn + k.y * c;
    *(float2*)&Q[base] = qo;
    *(float2*)&K[base] = ko;
}

// ===========================================================================
// Tensor-core flash attention (causal, tf32 mma.sync).
// CTA = (bh, 128-row q tile), 256 threads = 8 warps; warp w owns q rows w*16..+15.
// K-tile = 64 cols. Q fragments live in registers; K/V double-buffered cp.async.
// Strides chosen for conflict-free scalar fragment LDS:
//   Ks/Ps stride 68 (bank pattern 4g+t / 4g+2t), Vs stride 72 (pattern 8t+g).
// ===========================================================================
#define KSTR 68
#define VSTR 72
#define PSTR 68
#define AT_KS_FLOATS (64 * KSTR)          // 4352
#define AT_VS_FLOATS (64 * VSTR)          // 4608
#define AT_PS_FLOATS (128 * PSTR)         // 8704
#define AT_SMEM_FLOATS (2 * AT_KS_FLOATS + 2 * AT_VS_FLOATS + AT_PS_FLOATS)
#define AT_SMEM_BYTES (AT_SMEM_FLOATS * 4)   // 106496 B

__global__ __launch_bounds__(256, 1)
void attn_tc(const float* __restrict__ Q,
             const float* __restrict__ K,
             const float* __restrict__ V,
             float* __restrict__ C)
{
    extern __shared__ __align__(16) float sm[];
    float* KsB[2] = {sm, sm + AT_KS_FLOATS};
    float* VsB[2] = {sm + 2 * AT_KS_FLOATS, sm + 2 * AT_KS_FLOATS + AT_VS_FLOATS};
    float* Ps = sm + 2 * AT_KS_FLOATS + 2 * AT_VS_FLOATS;

    const int bh = blockIdx.y;
    const int qt = gridDim.x - 1 - blockIdx.x;   // heavy tiles first
    const int q0 = qt * 128;
    const int tid = threadIdx.x;
    const int wid = tid >> 5;
    const int lane = tid & 31;
    const int g = lane >> 2;
    const int t = lane & 3;
    const int rb = wid * 16;                     // warp's local q-row base

    const float* Qb = Q + (((size_t)bh * SEQ) + q0) * HDIM;
    const float* Kh = K + ((size_t)bh * SEQ) * HDIM;
    const float* Vh = V + ((size_t)bh * SEQ) * HDIM;

    // stage Q through the Ps buffer, then load fragments to registers (scaled)
    {
#pragma unroll
        for (int i = 0; i < 8; i++) {
            int idx = tid + i * 256;             // 2048 chunks of 16B
            int row = idx >> 4;
            int ch = idx & 15;
            *(float4*)&Ps[row * PSTR + ch * 4] = *(const float4*)&Qb[row * HDIM + ch * 4];
        }
    }
    __syncthreads();

    uint32_t qfr[8][4];
#pragma unroll
    for (int ks = 0; ks < 8; ks++) {
        int d0 = ks * 8;
        qfr[ks][0] = f2tf32(Ps[(rb + g) * PSTR + d0 + t] * 0.125f);
        qfr[ks][1] = f2tf32(Ps[(rb + g + 8) * PSTR + d0 + t] * 0.125f);
        qfr[ks][2] = f2tf32(Ps[(rb + g) * PSTR + d0 + t + 4] * 0.125f);
        qfr[ks][3] = f2tf32(Ps[(rb + g + 8) * PSTR + d0 + t + 4] * 0.125f);
    }
    __syncthreads();

    float oa[8][4];
#pragma unroll
    for (int a = 0; a < 8; a++)
#pragma unroll
        for (int r = 0; r < 4; r++) oa[a][r] = 0.f;
    float m_i[2] = {-INFINITY, -INFINITY};
    float l_i[2] = {0.f, 0.f};

    const int nkt = (q0 + 128) >> 6;

    // prefetch tile 0
    {
        uint32_t kb = smem_u32(KsB[0]);
        uint32_t vb = smem_u32(VsB[0]);
#pragma unroll
        for (int i = 0; i < 4; i++) {
            int idx = tid + i * 256;             // 1024 chunks
            int row = idx >> 4;
            int ch = idx & 15;
            cp_async16(kb + (uint32_t)(row * KSTR + ch * 4) * 4,
                       &Kh[(size_t)row * HDIM + ch * 4]);
            cp_async16(vb + (uint32_t)(row * VSTR + ch * 4) * 4,
                       &Vh[(size_t)row * HDIM + ch * 4]);
        }
        CP_ASYNC_COMMIT();
    }

    for (int kt = 0; kt < nkt; kt++) {
        if (kt + 1 < nkt) {
            const int nk0 = (kt + 1) * 64;
            const int buf = (kt + 1) & 1;
            uint32_t kb = smem_u32(KsB[buf]);
            uint32_t vb = smem_u32(VsB[buf]);
#pragma unroll
            for (int i = 0; i < 4; i++) {
                int idx = tid + i * 256;
                int row = idx >> 4;
                int ch = idx & 15;
                cp_async16(kb + (uint32_t)(row * KSTR + ch * 4) * 4,
                           &Kh[(size_t)(nk0 + row) * HDIM + ch * 4]);
                cp_async16(vb + (uint32_t)(row * VSTR + ch * 4) * 4,
                           &Vh[(size_t)(nk0 + row) * HDIM + ch * 4]);
            }
            CP_ASYNC_COMMIT();
            asm volatile("cp.async.wait_group 1;" ::: "memory");
        } else {
            asm volatile("cp.async.wait_group 0;" ::: "memory");
        }
        __syncthreads();

        const float* Ks = KsB[kt & 1];
        const float* Vs = VsB[kt & 1];
        const int k0g = kt * 64;

        // ---- S = Q K^T ----
        float sa[8][4];
#pragma unroll
        for (int a = 0; a < 8; a++)
#pragma unroll
            for (int r = 0; r < 4; r++) sa[a][r] = 0.f;

#pragma unroll
        for (int ks = 0; ks < 8; ks++) {
            const int d0 = ks * 8;
            uint32_t bfr[8][2];
#pragma unroll
            for (int a = 0; a < 8; a++) {
                int n = a * 8 + g;
                bfr[a][0] = f2tf32(Ks[n * KSTR + d0 + t]);
                bfr[a][1] = f2tf32(Ks[n * KSTR + d0 + t + 4]);
            }
#pragma unroll
            for (int a = 0; a < 8; a++)
                mma_tf32(sa[a][0], sa[a][1], sa[a][2], sa[a][3],
                         qfr[ks][0], qfr[ks][1], qfr[ks][2], qfr[ks][3],
                         bfr[a][0], bfr[a][1]);
        }

        // ---- causal mask (only near-diagonal tiles) ----
        if (k0g + 63 > q0 + rb) {
            const int r0g = q0 + rb + g;
            const int r1g = r0g + 8;
#pragma unroll
            for (int a = 0; a < 8; a++) {
                int c0 = k0g + a * 8 + 2 * t;
                int c1 = c0 + 1;
                if (c0 > r0g) sa[a][0] = -INFINITY;
                if (c1 > r0g) sa[a][1] = -INFINITY;
                if (c0 > r1g) sa[a][2] = -INFINITY;
                if (c1 > r1g) sa[a][3] = -INFINITY;
            }
        }

        // ---- online softmax (rows g and g+8) ----
#pragma unroll
        for (int rh = 0; rh < 2; rh++) {
            const int s0 = rh * 2;
            float mt = -INFINITY;
#pragma unroll
            for (int a = 0; a < 8; a++)
                mt = fmaxf(mt, fmaxf(sa[a][s0], sa[a][s0 + 1]));
            mt = fmaxf(mt, __shfl_xor_sync(0xffffffffu, mt, 1));
            mt = fmaxf(mt, __shfl_xor_sync(0xffffffffu, mt, 2));
            float mn = fmaxf(m_i[rh], mt);
            float corr = __expf(m_i[rh] - mn);
            float lt = 0.f;
#pragma unroll
            for (int a = 0; a < 8; a++) {
                sa[a][s0] = __expf(sa[a][s0] - mn);
                sa[a][s0 + 1] = __expf(sa[a][s0 + 1] - mn);
                lt += sa[a][s0] + sa[a][s0 + 1];
            }
            lt += __shfl_xor_sync(0xffffffffu, lt, 1);
            lt += __shfl_xor_sync(0xffffffffu, lt, 2);
            l_i[rh] = l_i[rh] * corr + lt;
            m_i[rh] = mn;
#pragma unroll
            for (int a = 0; a < 8; a++) {
                oa[a][s0] *= corr;
                oa[a][s0 + 1] *= corr;
            }
        }

        // ---- P to (warp-private) smem rows ----
#pragma unroll
        for (int a = 0; a < 8; a++) {
            *(float2*)&Ps[(rb + g) * PSTR + a * 8 + 2 * t] =
                make_float2(sa[a][0], sa[a][1]);
            *(float2*)&Ps[(rb + g + 8) * PSTR + a * 8 + 2 * t] =
                make_float2(sa[a][2], sa[a][3]);
        }
        __syncwarp();

        // ---- O += P V ----
#pragma unroll
        for (int ks = 0; ks < 8; ks++) {
            const int k0 = ks * 8;
            uint32_t pa0 = f2tf32(Ps[(rb + g) * PSTR + k0 + t]);
            uint32_t pa1 = f2tf32(Ps[(rb + g + 8) * PSTR + k0 + t]);
            uint32_t pa2 = f2tf32(Ps[(rb + g) * PSTR + k0 + t + 4]);
            uint32_t pa3 = f2tf32(Ps[(rb + g + 8) * PSTR + k0 + t + 4]);
#pragma unroll
            for (int a = 0; a < 8; a++) {
                uint32_t b0 = f2tf32(Vs[(k0 + t) * VSTR + a * 8 + g]);
                uint32_t b1 = f2tf32(Vs[(k0 + t + 4) * VSTR + a * 8 + g]);
                mma_tf32(oa[a][0], oa[a][1], oa[a][2], oa[a][3],
                         pa0, pa1, pa2, pa3, b0, b1);
            }
        }
        __syncthreads();
    }

    // ---- write context [B,S,D] ----
    const int b = bh >> 4;
    const int h = bh & 15;
    const float inv0 = 1.0f / l_i[0];
    const float inv1 = 1.0f / l_i[1];
    const int row0 = q0 + rb + g;
    const int row1 = row0 + 8;
#pragma unroll
    for (int a = 0; a < 8; a++) {
        int d = h * HDIM + a * 8 + 2 * t;
        *(float2*)&C[((size_t)b * SEQ + row0) * DMODEL + d] =
            make_float2(oa[a][0] * inv0, oa[a][1] * inv0);
        *(float2*)&C[((size_t)b * SEQ + row1) * DMODEL + d] =
            make_float2(oa[a][2] * inv1, oa[a][3] * inv1);
    }
}

// ---------------------------------------------------------------------------
// Launch
// ---------------------------------------------------------------------------
extern "C" void kernel_launch(void* const* d_in, const int* in_sizes, int n_in,
                              void* d_out, int out_size)
{
    const float* x  = (const float*)d_in[0];
    const float* Wq = (const float*)d_in[1];
    const float* bq = (const float*)d_in[2];
    const float* Wk = (const float*)d_in[3];
    const float* bk = (const float*)d_in[4];
    const float* Wv = (const float*)d_in[5];
    const float* bv = (const float*)d_in[6];
    const float* Wo = (const float*)d_in[7];
    const float* bo = (const float*)d_in[8];
    float* out = (float*)d_out;

    float *Q, *K, *V, *C;
    cudaGetSymbolAddress((void**)&Q, g_Q);
    cudaGetSymbolAddress((void**)&K, g_K);
    cudaGetSymbolAddress((void**)&V, g_V);
    cudaGetSymbolAddress((void**)&C, g_C);

    static int attr_set = 0;
    if (!attr_set) {
        cudaFuncSetAttribute(attn_tc,
                             cudaFuncAttributeMaxDynamicSharedMemorySize,
                             AT_SMEM_BYTES);
        cudaFuncSetAttribute(gemm_tc,
                             cudaFuncAttributeMaxDynamicSharedMemorySize,
                             SM_TOTAL);
        attr_set = 1;
    }

    dim3 ggrid(DMODEL / TBN, MROWS / TBM);  // (8, 32)
    gemm_tc<<<ggrid, 256, SM_TOTAL>>>(x, Wq, bq, Q, 1);
    gemm_tc<<<ggrid, 256, SM_TOTAL>>>(x, Wk, bk, K, 1);
    gemm_tc<<<ggrid, 256, SM_TOTAL>>>(x, Wv, bv, V, 1);

    int rope_threads = BH * SEQ * (HDIM / 2);
    rope_kernel<<<(rope_threads + 255) / 256, 256>>>(Q, K);

    dim3 agrid(SEQ / 128, BH);  // (16, 32)
    attn_tc<<<agrid, 256, AT_SMEM_BYTES>>>(Q, K, V, C);

    gemm_tc<<<ggrid, 256, SM_TOTAL>>>(C, Wo, bo, out, 0);
}

// round 5
// speedup vs baseline: 4.9763x; 1.9206x over previous
#include <cuda_runtime.h>
#include <cuda_fp16.h>
#include <math.h>
#include <cstdint>

// Problem constants
#define BATCH 2
#define SEQ 2048
#define DMODEL 1024
#define NHEADS 16
#define HDIM 64
#define BH (BATCH*NHEADS)          // 32
#define MROWS (BATCH*SEQ)          // 4096

// fp16 scratch (static device arrays -- no allocation allowed)
__device__ __half g_xh[MROWS * DMODEL];
__device__ __half g_Wqh[DMODEL * DMODEL];
__device__ __half g_Wkh[DMODEL * DMODEL];
__device__ __half g_Wvh[DMODEL * DMODEL];
__device__ __half g_Woh[DMODEL * DMODEL];
__device__ __half g_Qh[BH * SEQ * HDIM];   // roped + scaled
__device__ __half g_Kh[BH * SEQ * HDIM];   // roped
__device__ __half g_Vh[BH * SEQ * HDIM];
__device__ __half g_Ch[MROWS * DMODEL];    // context [B,S,D]

// ===========================================================================
// Helpers
// ===========================================================================
__device__ __forceinline__ void mma_f16(float& d0, float& d1, float& d2, float& d3,
                                        uint32_t a0, uint32_t a1, uint32_t a2, uint32_t a3,
                                        uint32_t b0, uint32_t b1) {
    asm volatile(
        "mma.sync.aligned.m16n8k16.row.col.f32.f16.f16.f32 "
        "{%0,%1,%2,%3}, {%4,%5,%6,%7}, {%8,%9}, {%0,%1,%2,%3};"
        : "+f"(d0), "+f"(d1), "+f"(d2), "+f"(d3)
        : "r"(a0), "r"(a1), "r"(a2), "r"(a3), "r"(b0), "r"(b1));
}

__device__ __forceinline__ void ldmatrix_x2_trans(uint32_t& r0, uint32_t& r1,
                                                  uint32_t addr) {
    asm volatile("ldmatrix.sync.aligned.m8n8.x2.trans.shared.b16 {%0,%1}, [%2];"
                 : "=r"(r0), "=r"(r1) : "r"(addr));
}

__device__ __forceinline__ void cp_async16(uint32_t smem_addr, const void* gmem) {
    asm volatile("cp.async.cg.shared.global [%0], [%1], 16;"
                 :: "r"(smem_addr), "l"(gmem) : "memory");
}
#define CP_ASYNC_COMMIT() asm volatile("cp.async.commit_group;" ::: "memory")

__device__ __forceinline__ uint32_t smem_u32(const void* p) {
    uint32_t a;
    asm("{ .reg .u64 t; cvta.to.shared.u64 t, %1; cvt.u32.u64 %0, t; }"
        : "=r"(a) : "l"(p));
    return a;
}

__device__ __forceinline__ uint32_t h2u(__half2 h) {
    return *(uint32_t*)&h;
}

// ---------------------------------------------------------------------------
// fp32 -> fp16 conversion (vectorized)
// ---------------------------------------------------------------------------
__global__ __launch_bounds__(256) void cvt_f16(const float* __restrict__ in,
                                               __half* __restrict__ out, int n4)
{
    int i = blockIdx.x * blockDim.x + threadIdx.x;
    if (i >= n4) return;
    float4 v = *(const float4*)&in[i * 4];
    __half2 lo = __floats2half2_rn(v.x, v.y);
    __half2 hi = __floats2half2_rn(v.z, v.w);
    *(__half2*)&out[i * 4] = lo;
    *(__half2*)&out[i * 4 + 2] = hi;
}

// ===========================================================================
// fp16 mma GEMM: out[m,n] = sum_k A[m,k] * W[n,k] + bias[n]
// A: [M,1024] fp16 row-major, W: [1024,1024] fp16 row-major.
// CTA 128x128, BK=32 halves, 8 warps (2M x 4N), warp tile 64x32.
// mode: 0 = fp32 out row-major; 1 = Q (rope + 0.125 scale, fp16 head layout);
//       2 = K (rope, fp16 head layout); 3 = V (fp16 head layout)
// ===========================================================================
#define TBM 128
#define TBN 128
#define TBK 32                    // halves per chunk
#define NCH (DMODEL / TBK)        // 32
#define HSTR 40                   // halves per smem row (pad 32->40)
#define STAGE_H (TBM * HSTR)      // 5120 halves = 10240 B
#define GSM_BYTES (4 * STAGE_H * 2)   // A0,B0,A1,B1 = 40960 B

__global__ __launch_bounds__(256)
void gemm_h(const __half* __restrict__ A,
            const __half* __restrict__ W,
            const float* __restrict__ bias,
            float* __restrict__ outf,
            __half* __restrict__ outh,
            int mode)
{
    extern __shared__ __align__(16) __half smh[];
    __half* As[2] = {smh, smh + 2 * STAGE_H};
    __half* Bs[2] = {smh + STAGE_H, smh + 3 * STAGE_H};

    const int tid = threadIdx.x;
    const int wid = tid >> 5;
    const int lane = tid & 31;
    const int wm = wid & 1;
    const int wn = wid >> 1;
    const int g = lane >> 2;
    const int t = lane & 3;

    const int row0 = blockIdx.y * TBM;
    const int col0 = blockIdx.x * TBN;

    // loader: each thread does 2x16B per matrix; row = tid>>1, half-row = tid&1
    const int lrow = tid >> 1;
    const int lhf = (tid & 1) * 16;   // halves offset (16 halves = 32B)

    float acc[4][4][4];
#pragma unroll
    for (int i = 0; i < 4; i++)
#pragma unroll
        for (int j = 0; j < 4; j++)
#pragma unroll
            for (int r = 0; r < 4; r++) acc[i][j][r] = 0.f;

    {
        uint32_t abase = smem_u32(As[0]);
        uint32_t bbase = smem_u32(Bs[0]);
        uint32_t soff = (uint32_t)(lrow * HSTR + lhf) * 2;
        cp_async16(abase + soff, &A[(size_t)(row0 + lrow) * DMODEL + lhf]);
        cp_async16(abase + soff + 16, &A[(size_t)(row0 + lrow) * DMODEL + lhf + 8]);
        cp_async16(bbase + soff, &W[(size_t)(col0 + lrow) * DMODEL + lhf]);
        cp_async16(bbase + soff + 16, &W[(size_t)(col0 + lrow) * DMODEL + lhf + 8]);
        CP_ASYNC_COMMIT();
    }

    for (int c = 0; c < NCH; c++) {
        if (c + 1 < NCH) {
            const int k0 = (c + 1) * TBK;
            const int buf = (c + 1) & 1;
            uint32_t abase = smem_u32(As[buf]);
            uint32_t bbase = smem_u32(Bs[buf]);
            uint32_t soff = (uint32_t)(lrow * HSTR + lhf) * 2;
            cp_async16(abase + soff, &A[(size_t)(row0 + lrow) * DMODEL + k0 + lhf]);
            cp_async16(abase + soff + 16, &A[(size_t)(row0 + lrow) * DMODEL + k0 + lhf + 8]);
            cp_async16(bbase + soff, &W[(size_t)(col0 + lrow) * DMODEL + k0 + lhf]);
            cp_async16(bbase + soff + 16, &W[(size_t)(col0 + lrow) * DMODEL + k0 + lhf + 8]);
            CP_ASYNC_COMMIT();
            asm volatile("cp.async.wait_group 1;" ::: "memory");
        } else {
            asm volatile("cp.async.wait_group 0;" ::: "memory");
        }
        __syncthreads();

        const __half* Ash = As[c & 1];
        const __half* Bsh = Bs[c & 1];
#pragma unroll
        for (int ks = 0; ks < 2; ks++) {
            const int k0h = ks * 16;
            uint32_t afr[4][4];
#pragma unroll
            for (int am = 0; am < 4; am++) {
                int r = wm * 64 + am * 16 + g;
                afr[am][0] = *(const uint32_t*)&Ash[r * HSTR + k0h + 2 * t];
                afr[am][1] = *(const uint32_t*)&Ash[(r + 8) * HSTR + k0h + 2 * t];
                afr[am][2] = *(const uint32_t*)&Ash[r * HSTR + k0h + 2 * t + 8];
                afr[am][3] = *(const uint32_t*)&Ash[(r + 8) * HSTR + k0h + 2 * t + 8];
            }
            uint32_t bfr[4][2];
#pragma unroll
            for (int bn = 0; bn < 4; bn++) {
                int n = wn * 32 + bn * 8 + g;
                bfr[bn][0] = *(const uint32_t*)&Bsh[n * HSTR + k0h + 2 * t];
                bfr[bn][1] = *(const uint32_t*)&Bsh[n * HSTR + k0h + 2 * t + 8];
            }
#pragma unroll
            for (int am = 0; am < 4; am++)
#pragma unroll
                for (int bn = 0; bn < 4; bn++)
                    mma_f16(acc[am][bn][0], acc[am][bn][1],
                            acc[am][bn][2], acc[am][bn][3],
                            afr[am][0], afr[am][1], afr[am][2], afr[am][3],
                            bfr[bn][0], bfr[bn][1]);
        }
        __syncthreads();
    }

    // ---- epilogue ----
#pragma unroll
    for (int bn = 0; bn < 4; bn++) {
        const int n0 = col0 + wn * 32 + bn * 8 + 2 * t;   // even
        const float b0 = __ldg(&bias[n0]);
        const float b1 = __ldg(&bias[n0 + 1]);

        float invf = 0.f;
        if (mode == 1 || mode == 2) {
            int pair = (n0 & 63) >> 1;
            invf = powf(10000.0f, -(float)pair / 32.0f);
        }
#pragma unroll
        for (int am = 0; am < 4; am++) {
            const int r0 = row0 + wm * 64 + am * 16 + g;
#pragma unroll
            for (int rh = 0; rh < 2; rh++) {
                const int r = r0 + rh * 8;
                float v0 = acc[am][bn][rh * 2] + b0;
                float v1 = acc[am][bn][rh * 2 + 1] + b1;
                if (mode == 0) {
                    *(float2*)&outf[(size_t)r * DMODEL + n0] = make_float2(v0, v1);
                } else {
                    const int b = r >> 11;
                    const int s = r & (SEQ - 1);
                    const int h = n0 >> 6;
                    const int d = n0 & 63;
                    if (mode != 3) {
                        float sn, cs;
                        sincosf((float)s * invf, &sn, &cs);
                        float oe = v0 * cs - v1 * sn;
                        float oo = v0 * sn + v1 * cs;
                        if (mode == 1) { oe *= 0.125f; oo *= 0.125f; }
                        v0 = oe; v1 = oo;
                    }
                    __half2 hv = __floats2half2_rn(v0, v1);
                    *(__half2*)&outh[(((size_t)(b * NHEADS + h)) * SEQ + s) * HDIM + d] = hv;
                }
            }
        }
    }
}

// ===========================================================================
// fp16 tensor-core flash attention (causal).
// CTA = (bh, 128-row q tile), 8 warps; warp w owns q rows w*16..+15.
// K-tile 64. Q frags in regs from gmem; K/V double-buffered cp.async.
// K frags: direct half2 LDS (stride 72 halves -> bank 4g+t, conflict-free).
// V frags: ldmatrix.x2.trans. P: register-only (accumulator == A-fragment).
// ===========================================================================
#define KVSTR 72                              // halves per row
#define KV_TILE_H (64 * KVSTR)                // 4608 halves = 9216 B
#define AT_SMEM_BYTES (4 * KV_TILE_H * 2)     // K0,K1,V0,V1 = 36864 B

__global__ __launch_bounds__(256)
void attn_h(const __half* __restrict__ Q,
            const __half* __restrict__ K,
            const __half* __restrict__ V,
            __half* __restrict__ C)
{
    extern __shared__ __align__(16) __half smh[];
    __half* KsB[2] = {smh, smh + KV_TILE_H};
    __half* VsB[2] = {smh + 2 * KV_TILE_H, smh + 3 * KV_TILE_H};

    const int bh = blockIdx.y;
    const int qt = gridDim.x - 1 - blockIdx.x;   // heavy tiles first
    const int q0 = qt * 128;
    const int tid = threadIdx.x;
    const int wid = tid >> 5;
    const int lane = tid & 31;
    const int g = lane >> 2;
    const int t = lane & 3;
    const int rb = wid * 16;

    const __half* Qb = Q + (((size_t)bh * SEQ) + q0) * HDIM;
    const __half* Kh = K + ((size_t)bh * SEQ) * HDIM;
    const __half* Vh = V + ((size_t)bh * SEQ) * HDIM;

    // Q fragments straight from gmem (pre-roped, pre-scaled)
    uint32_t qfr[4][4];
#pragma unroll
    for (int ks = 0; ks < 4; ks++) {
        const int d0 = ks * 16;
        qfr[ks][0] = *(const uint32_t*)&Qb[(rb + g) * HDIM + d0 + 2 * t];
        qfr[ks][1] = *(const uint32_t*)&Qb[(rb + g + 8) * HDIM + d0 + 2 * t];
        qfr[ks][2] = *(const uint32_t*)&Qb[(rb + g) * HDIM + d0 + 2 * t + 8];
        qfr[ks][3] = *(const uint32_t*)&Qb[(rb + g + 8) * HDIM + d0 + 2 * t + 8];
    }

    float oa[8][4];
#pragma unroll
    for (int a = 0; a < 8; a++)
#pragma unroll
        for (int r = 0; r < 4; r++) oa[a][r] = 0.f;
    float m_i[2] = {-INFINITY, -INFINITY};
    float l_i[2] = {0.f, 0.f};

    const int nkt = (q0 + 128) >> 6;

    // loader: row = tid>>2 (0..63), 2x16B chunks at (tid&3)*32B
    const int lrow = tid >> 2;
    const int lhf = (tid & 3) * 16;    // halves

    {
        uint32_t kb = smem_u32(KsB[0]);
        uint32_t vb = smem_u32(VsB[0]);
        uint32_t soff = (uint32_t)(lrow * KVSTR + lhf) * 2;
        cp_async16(kb + soff, &Kh[(size_t)lrow * HDIM + lhf]);
        cp_async16(kb + soff + 16, &Kh[(size_t)lrow * HDIM + lhf + 8]);
        cp_async16(vb + soff, &Vh[(size_t)lrow * HDIM + lhf]);
        cp_async16(vb + soff + 16, &Vh[(size_t)lrow * HDIM + lhf + 8]);
        CP_ASYNC_COMMIT();
    }

    for (int kt = 0; kt < nkt; kt++) {
        if (kt + 1 < nkt) {
            const int nk0 = (kt + 1) * 64;
            const int buf = (kt + 1) & 1;
            uint32_t kb = smem_u32(KsB[buf]);
            uint32_t vb = smem_u32(VsB[buf]);
            uint32_t soff = (uint32_t)(lrow * KVSTR + lhf) * 2;
            cp_async16(kb + soff, &Kh[(size_t)(nk0 + lrow) * HDIM + lhf]);
            cp_async16(kb + soff + 16, &Kh[(size_t)(nk0 + lrow) * HDIM + lhf + 8]);
            cp_async16(vb + soff, &Vh[(size_t)(nk0 + lrow) * HDIM + lhf]);
            cp_async16(vb + soff + 16, &Vh[(size_t)(nk0 + lrow) * HDIM + lhf + 8]);
            CP_ASYNC_COMMIT();
            asm volatile("cp.async.wait_group 1;" ::: "memory");
        } else {
            asm volatile("cp.async.wait_group 0;" ::: "memory");
        }
        __syncthreads();

        const __half* Ks = KsB[kt & 1];
        const uint32_t vsb = smem_u32(VsB[kt & 1]);
        const int k0g = kt * 64;

        // ---- S = Q K^T ----
        float sa[8][4];
#pragma unroll
        for (int a = 0; a < 8; a++)
#pragma unroll
            for (int r = 0; r < 4; r++) sa[a][r] = 0.f;

#pragma unroll
        for (int ks = 0; ks < 4; ks++) {
            const int d0 = ks * 16;
#pragma unroll
            for (int a = 0; a < 8; a++) {
                int n = a * 8 + g;
                uint32_t b0 = *(const uint32_t*)&Ks[n * KVSTR + d0 + 2 * t];
                uint32_t b1 = *(const uint32_t*)&Ks[n * KVSTR + d0 + 2 * t + 8];
                mma_f16(sa[a][0], sa[a][1], sa[a][2], sa[a][3],
                        qfr[ks][0], qfr[ks][1], qfr[ks][2], qfr[ks][3], b0, b1);
            }
        }

        // ---- causal mask ----
        if (k0g + 63 > q0 + rb) {
            const int r0g = q0 + rb + g;
            const int r1g = r0g + 8;
#pragma unroll
            for (int a = 0; a < 8; a++) {
                int c0 = k0g + a * 8 + 2 * t;
                int c1 = c0 + 1;
                if (c0 > r0g) sa[a][0] = -INFINITY;
                if (c1 > r0g) sa[a][1] = -INFINITY;
                if (c0 > r1g) sa[a][2] = -INFINITY;
                if (c1 > r1g) sa[a][3] = -INFINITY;
            }
        }

        // ---- online softmax ----
#pragma unroll
        for (int rh = 0; rh < 2; rh++) {
            const int s0 = rh * 2;
            float mt = -INFINITY;
#pragma unroll
            for (int a = 0; a < 8; a++)
                mt = fmaxf(mt, fmaxf(sa[a][s0], sa[a][s0 + 1]));
            mt = fmaxf(mt, __shfl_xor_sync(0xffffffffu, mt, 1));
            mt = fmaxf(mt, __shfl_xor_sync(0xffffffffu, mt, 2));
            float mn = fmaxf(m_i[rh], mt);
            float corr = __expf(m_i[rh] - mn);
            float lt = 0.f;
#pragma unroll
            for (int a = 0; a < 8; a++) {
                sa[a][s0] = __expf(sa[a][s0] - mn);
                sa[a][s0 + 1] = __expf(sa[a][s0 + 1] - mn);
                lt += sa[a][s0] + sa[a][s0 + 1];
            }
            lt += __shfl_xor_sync(0xffffffffu, lt, 1);
            lt += __shfl_xor_sync(0xffffffffu, lt, 2);
            l_i[rh] = l_i[rh] * corr + lt;
            m_i[rh] = mn;
#pragma unroll
            for (int a = 0; a < 8; a++) {
                oa[a][s0] *= corr;
                oa[a][s0 + 1] *= corr;
            }
        }

        // ---- O += P V  (P built in registers from S accumulators) ----
#pragma unroll
        for (int kk = 0; kk < 4; kk++) {
            uint32_t pa0 = h2u(__floats2half2_rn(sa[2 * kk][0], sa[2 * kk][1]));
            uint32_t pa1 = h2u(__floats2half2_rn(sa[2 * kk][2], sa[2 * kk][3]));
            uint32_t pa2 = h2u(__floats2half2_rn(sa[2 * kk + 1][0], sa[2 * kk + 1][1]));
            uint32_t pa3 = h2u(__floats2half2_rn(sa[2 * kk + 1][2], sa[2 * kk + 1][3]));
            const uint32_t rowaddr = vsb +
                (uint32_t)((kk * 16 + (lane & 15)) * KVSTR) * 2;
#pragma unroll
            for (int a = 0; a < 8; a++) {
                uint32_t b0, b1;
                ldmatrix_x2_trans(b0, b1, rowaddr + a * 16);
                mma_f16(oa[a][0], oa[a][1], oa[a][2], oa[a][3],
                        pa0, pa1, pa2, pa3, b0, b1);
            }
        }
        __syncthreads();
    }

    // ---- write context fp16 [B,S,D] ----
    const int b = bh >> 4;
    const int h = bh & 15;
    const float inv0 = 1.0f / l_i[0];
    const float inv1 = 1.0f / l_i[1];
    const int row0 = q0 + rb + g;
    const int row1 = row0 + 8;
#pragma unroll
    for (int a = 0; a < 8; a++) {
        int d = h * HDIM + a * 8 + 2 * t;
        *(__half2*)&C[((size_t)b * SEQ + row0) * DMODEL + d] =
            __floats2half2_rn(oa[a][0] * inv0, oa[a][1] * inv0);
        *(__half2*)&C[((size_t)b * SEQ + row1) * DMODEL + d] =
            __floats2half2_rn(oa[a][2] * inv1, oa[a][3] * inv1);
    }
}

// ---------------------------------------------------------------------------
// Launch
// ---------------------------------------------------------------------------
extern "C" void kernel_launch(void* const* d_in, const int* in_sizes, int n_in,
                              void* d_out, int out_size)
{
    const float* x  = (const float*)d_in[0];
    const float* Wq = (const float*)d_in[1];
    const float* bq = (const float*)d_in[2];
    const float* Wk = (const float*)d_in[3];
    const float* bk = (const float*)d_in[4];
    const float* Wv = (const float*)d_in[5];
    const float* bv = (const float*)d_in[6];
    const float* Wo = (const float*)d_in[7];
    const float* bo = (const float*)d_in[8];
    float* out = (float*)d_out;

    __half *xh, *Wqh, *Wkh, *Wvh, *Woh, *Qh, *Kh, *Vh, *Ch;
    cudaGetSymbolAddress((void**)&xh, g_xh);
    cudaGetSymbolAddress((void**)&Wqh, g_Wqh);
    cudaGetSymbolAddress((void**)&Wkh, g_Wkh);
    cudaGetSymbolAddress((void**)&Wvh, g_Wvh);
    cudaGetSymbolAddress((void**)&Woh, g_Woh);
    cudaGetSymbolAddress((void**)&Qh, g_Qh);
    cudaGetSymbolAddress((void**)&Kh, g_Kh);
    cudaGetSymbolAddress((void**)&Vh, g_Vh);
    cudaGetSymbolAddress((void**)&Ch, g_Ch);

    static int attr_set = 0;
    if (!attr_set) {
        cudaFuncSetAttribute(attn_h,
                             cudaFuncAttributeMaxDynamicSharedMemorySize,
                             AT_SMEM_BYTES);
        cudaFuncSetAttribute(gemm_h,
                             cudaFuncAttributeMaxDynamicSharedMemorySize,
                             GSM_BYTES);
        attr_set = 1;
    }

    // converts
    const int XN4 = MROWS * DMODEL / 4;
    const int WN4 = DMODEL * DMODEL / 4;
    cvt_f16<<<(XN4 + 255) / 256, 256>>>(x, xh, XN4);
    cvt_f16<<<(WN4 + 255) / 256, 256>>>(Wq, Wqh, WN4);
    cvt_f16<<<(WN4 + 255) / 256, 256>>>(Wk, Wkh, WN4);
    cvt_f16<<<(WN4 + 255) / 256, 256>>>(Wv, Wvh, WN4);
    cvt_f16<<<(WN4 + 255) / 256, 256>>>(Wo, Woh, WN4);

    dim3 ggrid(DMODEL / TBN, MROWS / TBM);  // (8, 32)
    gemm_h<<<ggrid, 256, GSM_BYTES>>>(xh, Wqh, bq, nullptr, Qh, 1);
    gemm_h<<<ggrid, 256, GSM_BYTES>>>(xh, Wkh, bk, nullptr, Kh, 2);
    gemm_h<<<ggrid, 256, GSM_BYTES>>>(xh, Wvh, bv, nullptr, Vh, 3);

    dim3 agrid(SEQ / 128, BH);  // (16, 32)
    attn_h<<<agrid, 256, AT_SMEM_BYTES>>>(Qh, Kh, Vh, Ch);

    gemm_h<<<ggrid, 256, GSM_BYTES>>>(Ch, Woh, bo, out, nullptr, 0);
}

// round 6
// speedup vs baseline: 5.8018x; 1.1659x over previous
#include <cuda_runtime.h>
#include <cuda_fp16.h>
#include <math.h>
#include <cstdint>

// Problem constants
#define BATCH 2
#define SEQ 2048
#define DMODEL 1024
#define NHEADS 16
#define HDIM 64
#define BH (BATCH*NHEADS)          // 32
#define MROWS (BATCH*SEQ)          // 4096

// fp16 scratch (static device arrays -- no allocation allowed)
__device__ __half g_xh[MROWS * DMODEL];
__device__ __half g_Wqh[DMODEL * DMODEL];
__device__ __half g_Wkh[DMODEL * DMODEL];
__device__ __half g_Wvh[DMODEL * DMODEL];
__device__ __half g_Woh[DMODEL * DMODEL];
__device__ __half g_Qh[BH * SEQ * HDIM];   // roped + scaled
__device__ __half g_Kh[BH * SEQ * HDIM];   // roped
__device__ __half g_Vh[BH * SEQ * HDIM];
__device__ __half g_Ch[MROWS * DMODEL];    // context [B,S,D]

// ===========================================================================
// Helpers
// ===========================================================================
__device__ __forceinline__ void mma_f16(float& d0, float& d1, float& d2, float& d3,
                                        uint32_t a0, uint32_t a1, uint32_t a2, uint32_t a3,
                                        uint32_t b0, uint32_t b1) {
    asm volatile(
        "mma.sync.aligned.m16n8k16.row.col.f32.f16.f16.f32 "
        "{%0,%1,%2,%3}, {%4,%5,%6,%7}, {%8,%9}, {%0,%1,%2,%3};"
        : "+f"(d0), "+f"(d1), "+f"(d2), "+f"(d3)
        : "r"(a0), "r"(a1), "r"(a2), "r"(a3), "r"(b0), "r"(b1));
}

__device__ __forceinline__ void ldmatrix_x4(uint32_t& r0, uint32_t& r1,
                                            uint32_t& r2, uint32_t& r3,
                                            uint32_t addr) {
    asm volatile("ldmatrix.sync.aligned.m8n8.x4.shared.b16 {%0,%1,%2,%3}, [%4];"
                 : "=r"(r0), "=r"(r1), "=r"(r2), "=r"(r3) : "r"(addr));
}

__device__ __forceinline__ void ldmatrix_x2_trans(uint32_t& r0, uint32_t& r1,
                                                  uint32_t addr) {
    asm volatile("ldmatrix.sync.aligned.m8n8.x2.trans.shared.b16 {%0,%1}, [%2];"
                 : "=r"(r0), "=r"(r1) : "r"(addr));
}

__device__ __forceinline__ void cp_async16(uint32_t smem_addr, const void* gmem) {
    asm volatile("cp.async.cg.shared.global [%0], [%1], 16;"
                 :: "r"(smem_addr), "l"(gmem) : "memory");
}
#define CP_ASYNC_COMMIT() asm volatile("cp.async.commit_group;" ::: "memory")

__device__ __forceinline__ uint32_t smem_u32(const void* p) {
    uint32_t a;
    asm("{ .reg .u64 t; cvta.to.shared.u64 t, %1; cvt.u32.u64 %0, t; }"
        : "=r"(a) : "l"(p));
    return a;
}

__device__ __forceinline__ uint32_t h2u(__half2 h) {
    return *(uint32_t*)&h;
}

// ---------------------------------------------------------------------------
// Fused fp32 -> fp16 conversion for x + all 4 weights (one launch)
// ---------------------------------------------------------------------------
#define XN4 (MROWS * DMODEL / 4)      // 1048576
#define WN4 (DMODEL * DMODEL / 4)     // 262144
#define TOT4 (XN4 + 4 * WN4)          // 2097152

__global__ __launch_bounds__(256) void cvt_all(
    const float* __restrict__ x,
    const float* __restrict__ wq, const float* __restrict__ wk,
    const float* __restrict__ wv, const float* __restrict__ wo,
    __half* __restrict__ xh,
    __half* __restrict__ wqh, __half* __restrict__ wkh,
    __half* __restrict__ wvh, __half* __restrict__ woh)
{
    int i = blockIdx.x * blockDim.x + threadIdx.x;
    if (i >= TOT4) return;
    const float* src;
    __half* dst;
    int off;
    if (i < XN4) {
        src = x; dst = xh; off = i;
    } else {
        int j = i - XN4;
        int w = j >> 18;               // / WN4
        off = j & (WN4 - 1);
        src = (w == 0) ? wq : (w == 1) ? wk : (w == 2) ? wv : wo;
        dst = (w == 0) ? wqh : (w == 1) ? wkh : (w == 2) ? wvh : woh;
    }
    float4 v = *(const float4*)&src[(size_t)off * 4];
    *(__half2*)&dst[(size_t)off * 4] = __floats2half2_rn(v.x, v.y);
    *(__half2*)&dst[(size_t)off * 4 + 2] = __floats2half2_rn(v.z, v.w);
}

// ===========================================================================
// fp16 mma GEMM: out[m,n] = sum_k A[m,k] * W[n,k] + bias[n]
// CTA 128x128, BK=32 halves, 8 warps (2M x 4N), warp tile 64x32, ldmatrix.x4.
// fused=1: blockIdx.z selects (Wq->Q rope+scale | Wk->K rope | Wv->V), fp16 out.
// fused=0: W0/b0 -> fp32 row-major outf.
// ===========================================================================
#define TBM 128
#define TBN 128
#define TBK 32
#define NCH (DMODEL / TBK)
#define HSTR 40                   // halves per smem row (pad 32->40); 80B row
#define STAGE_H (TBM * HSTR)
#define GSM_BYTES (4 * STAGE_H * 2)   // 40960 B

__global__ __launch_bounds__(256)
void gemm_h(const __half* __restrict__ A,
            const __half* __restrict__ W0, const __half* __restrict__ W1,
            const __half* __restrict__ W2,
            const float* __restrict__ b0p, const float* __restrict__ b1p,
            const float* __restrict__ b2p,
            float* __restrict__ outf,
            __half* __restrict__ o0, __half* __restrict__ o1,
            __half* __restrict__ o2,
            int fused)
{
    extern __shared__ __align__(16) __half smh[];
    __half* As[2] = {smh, smh + 2 * STAGE_H};
    __half* Bs[2] = {smh + STAGE_H, smh + 3 * STAGE_H};

    const int z = fused ? blockIdx.z : 0;
    const int mode = fused ? (z + 1) : 0;
    const __half* W = (z == 0) ? W0 : (z == 1) ? W1 : W2;
    const float* bias = (z == 0) ? b0p : (z == 1) ? b1p : b2p;
    __half* outh = (z == 0) ? o0 : (z == 1) ? o1 : o2;

    const int tid = threadIdx.x;
    const int wid = tid >> 5;
    const int lane = tid & 31;
    const int wm = wid & 1;
    const int wn = wid >> 1;
    const int g = lane >> 2;
    const int t = lane & 3;

    const int row0 = blockIdx.y * TBM;
    const int col0 = blockIdx.x * TBN;

    // loader: row = tid>>1, 2x16B at (tid&1)*32B
    const int lrow = tid >> 1;
    const int lhf = (tid & 1) * 16;

    // ldmatrix lane decomposition
    const int lr8 = lane & 7;
    const int lg8 = (lane >> 3) & 1;
    const int lk8 = (lane >> 4) & 1;

    float acc[4][4][4];
#pragma unroll
    for (int i = 0; i < 4; i++)
#pragma unroll
        for (int j = 0; j < 4; j++)
#pragma unroll
            for (int r = 0; r < 4; r++) acc[i][j][r] = 0.f;

    {
        uint32_t abase = smem_u32(As[0]);
        uint32_t bbase = smem_u32(Bs[0]);
        uint32_t soff = (uint32_t)(lrow * HSTR + lhf) * 2;
        cp_async16(abase + soff, &A[(size_t)(row0 + lrow) * DMODEL + lhf]);
        cp_async16(abase + soff + 16, &A[(size_t)(row0 + lrow) * DMODEL + lhf + 8]);
        cp_async16(bbase + soff, &W[(size_t)(col0 + lrow) * DMODEL + lhf]);
        cp_async16(bbase + soff + 16, &W[(size_t)(col0 + lrow) * DMODEL + lhf + 8]);
        CP_ASYNC_COMMIT();
    }

    for (int c = 0; c < NCH; c++) {
        if (c + 1 < NCH) {
            const int k0 = (c + 1) * TBK;
            const int buf = (c + 1) & 1;
            uint32_t abase = smem_u32(As[buf]);
            uint32_t bbase = smem_u32(Bs[buf]);
            uint32_t soff = (uint32_t)(lrow * HSTR + lhf) * 2;
            cp_async16(abase + soff, &A[(size_t)(row0 + lrow) * DMODEL + k0 + lhf]);
            cp_async16(abase + soff + 16, &A[(size_t)(row0 + lrow) * DMODEL + k0 + lhf + 8]);
            cp_async16(bbase + soff, &W[(size_t)(col0 + lrow) * DMODEL + k0 + lhf]);
            cp_async16(bbase + soff + 16, &W[(size_t)(col0 + lrow) * DMODEL + k0 + lhf + 8]);
            CP_ASYNC_COMMIT();
            asm volatile("cp.async.wait_group 1;" ::: "memory");
        } else {
            asm volatile("cp.async.wait_group 0;" ::: "memory");
        }
        __syncthreads();

        const uint32_t asb = smem_u32(As[c & 1]);
        const uint32_t bsb = smem_u32(Bs[c & 1]);
#pragma unroll
        for (int ks = 0; ks < 2; ks++) {
            const int k0h = ks * 16;
            const uint32_t acol = (uint32_t)(k0h + lk8 * 8) * 2;
            uint32_t afr[4][4];
#pragma unroll
            for (int am = 0; am < 4; am++) {
                int r = wm * 64 + am * 16 + lr8 + lg8 * 8;
                ldmatrix_x4(afr[am][0], afr[am][1], afr[am][2], afr[am][3],
                            asb + (uint32_t)(r * HSTR) * 2 + acol);
            }
            uint32_t bfr[4][2];
#pragma unroll
            for (int bnp = 0; bnp < 2; bnp++) {
                int n = wn * 32 + bnp * 16 + lr8 + lg8 * 8;
                ldmatrix_x4(bfr[2 * bnp][0], bfr[2 * bnp + 1][0],
                            bfr[2 * bnp][1], bfr[2 * bnp + 1][1],
                            bsb + (uint32_t)(n * HSTR) * 2 + acol);
            }
#pragma unroll
            for (int am = 0; am < 4; am++)
#pragma unroll
                for (int bn = 0; bn < 4; bn++)
                    mma_f16(acc[am][bn][0], acc[am][bn][1],
                            acc[am][bn][2], acc[am][bn][3],
                            afr[am][0], afr[am][1], afr[am][2], afr[am][3],
                            bfr[bn][0], bfr[bn][1]);
        }
        __syncthreads();
    }

    // ---- epilogue ----
#pragma unroll
    for (int bn = 0; bn < 4; bn++) {
        const int n0 = col0 + wn * 32 + bn * 8 + 2 * t;
        const float b0 = __ldg(&bias[n0]);
        const float b1 = __ldg(&bias[n0 + 1]);

        float invf = 0.f;
        if (mode == 1 || mode == 2) {
            int pair = (n0 & 63) >> 1;
            invf = powf(10000.0f, -(float)pair / 32.0f);
        }
#pragma unroll
        for (int am = 0; am < 4; am++) {
            const int r0 = row0 + wm * 64 + am * 16 + g;
#pragma unroll
            for (int rh = 0; rh < 2; rh++) {
                const int r = r0 + rh * 8;
                float v0 = acc[am][bn][rh * 2] + b0;
                float v1 = acc[am][bn][rh * 2 + 1] + b1;
                if (mode == 0) {
                    *(float2*)&outf[(size_t)r * DMODEL + n0] = make_float2(v0, v1);
                } else {
                    const int b = r >> 11;
                    const int s = r & (SEQ - 1);
                    const int h = n0 >> 6;
                    const int d = n0 & 63;
                    if (mode != 3) {
                        float sn, cs;
                        sincosf((float)s * invf, &sn, &cs);
                        float oe = v0 * cs - v1 * sn;
                        float oo = v0 * sn + v1 * cs;
                        if (mode == 1) { oe *= 0.125f; oo *= 0.125f; }
                        v0 = oe; v1 = oo;
                    }
                    __half2 hv = __floats2half2_rn(v0, v1);
                    *(__half2*)&outh[(((size_t)(b * NHEADS + h)) * SEQ + s) * HDIM + d] = hv;
                }
            }
        }
    }
}

// ===========================================================================
// fp16 tensor-core flash attention (causal).
// CTA = (bh, 128-row q tile), 8 warps; warp w owns q rows w*16..+15.
// K frags via ldmatrix.x4 (stride 72 halves = 144B rows, conflict-free).
// V frags via ldmatrix.x2.trans. P register-only.
// ===========================================================================
#define KVSTR 72
#define KV_TILE_H (64 * KVSTR)
#define AT_SMEM_BYTES (4 * KV_TILE_H * 2)     // 36864 B

__global__ __launch_bounds__(256)
void attn_h(const __half* __restrict__ Q,
            const __half* __restrict__ K,
            const __half* __restrict__ V,
            __half* __restrict__ C)
{
    extern __shared__ __align__(16) __half smh[];
    __half* KsB[2] = {smh, smh + KV_TILE_H};
    __half* VsB[2] = {smh + 2 * KV_TILE_H, smh + 3 * KV_TILE_H};

    const int bh = blockIdx.y;
    const int qt = gridDim.x - 1 - blockIdx.x;   // heavy tiles first
    const int q0 = qt * 128;
    const int tid = threadIdx.x;
    const int wid = tid >> 5;
    const int lane = tid & 31;
    const int g = lane >> 2;
    const int t = lane & 3;
    const int rb = wid * 16;

    const int lr8 = lane & 7;
    const int lg8 = (lane >> 3) & 1;
    const int lk8 = (lane >> 4) & 1;

    const __half* Qb = Q + (((size_t)bh * SEQ) + q0) * HDIM;
    const __half* Kh = K + ((size_t)bh * SEQ) * HDIM;
    const __half* Vh = V + ((size_t)bh * SEQ) * HDIM;

    // Q fragments straight from gmem (pre-roped, pre-scaled)
    uint32_t qfr[4][4];
#pragma unroll
    for (int ks = 0; ks < 4; ks++) {
        const int d0 = ks * 16;
        qfr[ks][0] = *(const uint32_t*)&Qb[(rb + g) * HDIM + d0 + 2 * t];
        qfr[ks][1] = *(const uint32_t*)&Qb[(rb + g + 8) * HDIM + d0 + 2 * t];
        qfr[ks][2] = *(const uint32_t*)&Qb[(rb + g) * HDIM + d0 + 2 * t + 8];
        qfr[ks][3] = *(const uint32_t*)&Qb[(rb + g + 8) * HDIM + d0 + 2 * t + 8];
    }

    float oa[8][4];
#pragma unroll
    for (int a = 0; a < 8; a++)
#pragma unroll
        for (int r = 0; r < 4; r++) oa[a][r] = 0.f;
    float m_i[2] = {-INFINITY, -INFINITY};
    float l_i[2] = {0.f, 0.f};

    const int nkt = (q0 + 128) >> 6;

    const int lrow = tid >> 2;
    const int lhf = (tid & 3) * 16;

    {
        uint32_t kb = smem_u32(KsB[0]);
        uint32_t vb = smem_u32(VsB[0]);
        uint32_t soff = (uint32_t)(lrow * KVSTR + lhf) * 2;
        cp_async16(kb + soff, &Kh[(size_t)lrow * HDIM + lhf]);
        cp_async16(kb + soff + 16, &Kh[(size_t)lrow * HDIM + lhf + 8]);
        cp_async16(vb + soff, &Vh[(size_t)lrow * HDIM + lhf]);
        cp_async16(vb + soff + 16, &Vh[(size_t)lrow * HDIM + lhf + 8]);
        CP_ASYNC_COMMIT();
    }

    for (int kt = 0; kt < nkt; kt++) {
        if (kt + 1 < nkt) {
            const int nk0 = (kt + 1) * 64;
            const int buf = (kt + 1) & 1;
            uint32_t kb = smem_u32(KsB[buf]);
            uint32_t vb = smem_u32(VsB[buf]);
            uint32_t soff = (uint32_t)(lrow * KVSTR + lhf) * 2;
            cp_async16(kb + soff, &Kh[(size_t)(nk0 + lrow) * HDIM + lhf]);
            cp_async16(kb + soff + 16, &Kh[(size_t)(nk0 + lrow) * HDIM + lhf + 8]);
            cp_async16(vb + soff, &Vh[(size_t)(nk0 + lrow) * HDIM + lhf]);
            cp_async16(vb + soff + 16, &Vh[(size_t)(nk0 + lrow) * HDIM + lhf + 8]);
            CP_ASYNC_COMMIT();
            asm volatile("cp.async.wait_group 1;" ::: "memory");
        } else {
            asm volatile("cp.async.wait_group 0;" ::: "memory");
        }
        __syncthreads();

        const uint32_t ksb = smem_u32(KsB[kt & 1]);
        const uint32_t vsb = smem_u32(VsB[kt & 1]);
        const int k0g = kt * 64;

        // ---- S = Q K^T (K frags via ldmatrix.x4) ----
        float sa[8][4];
#pragma unroll
        for (int a = 0; a < 8; a++)
#pragma unroll
            for (int r = 0; r < 4; r++) sa[a][r] = 0.f;

#pragma unroll
        for (int ks = 0; ks < 4; ks++) {
            const int d0 = ks * 16;
            const uint32_t kcol = (uint32_t)(d0 + lk8 * 8) * 2;
            uint32_t bk[8][2];
#pragma unroll
            for (int ap = 0; ap < 4; ap++) {
                int n = ap * 16 + lr8 + lg8 * 8;
                ldmatrix_x4(bk[2 * ap][0], bk[2 * ap + 1][0],
                            bk[2 * ap][1], bk[2 * ap + 1][1],
                            ksb + (uint32_t)(n * KVSTR) * 2 + kcol);
            }
#pragma unroll
            for (int a = 0; a < 8; a++)
                mma_f16(sa[a][0], sa[a][1], sa[a][2], sa[a][3],
                        qfr[ks][0], qfr[ks][1], qfr[ks][2], qfr[ks][3],
                        bk[a][0], bk[a][1]);
        }

        // ---- causal mask ----
        if (k0g + 63 > q0 + rb) {
            const int r0g = q0 + rb + g;
            const int r1g = r0g + 8;
#pragma unroll
            for (int a = 0; a < 8; a++) {
                int c0 = k0g + a * 8 + 2 * t;
                int c1 = c0 + 1;
                if (c0 > r0g) sa[a][0] = -INFINITY;
                if (c1 > r0g) sa[a][1] = -INFINITY;
                if (c0 > r1g) sa[a][2] = -INFINITY;
                if (c1 > r1g) sa[a][3] = -INFINITY;
            }
        }

        // ---- online softmax ----
#pragma unroll
        for (int rh = 0; rh < 2; rh++) {
            const int s0 = rh * 2;
            float mt = -INFINITY;
#pragma unroll
            for (int a = 0; a < 8; a++)
                mt = fmaxf(mt, fmaxf(sa[a][s0], sa[a][s0 + 1]));
            mt = fmaxf(mt, __shfl_xor_sync(0xffffffffu, mt, 1));
            mt = fmaxf(mt, __shfl_xor_sync(0xffffffffu, mt, 2));
            float mn = fmaxf(m_i[rh], mt);
            float corr = __expf(m_i[rh] - mn);
            float lt = 0.f;
#pragma unroll
            for (int a = 0; a < 8; a++) {
                sa[a][s0] = __expf(sa[a][s0] - mn);
                sa[a][s0 + 1] = __expf(sa[a][s0 + 1] - mn);
                lt += sa[a][s0] + sa[a][s0 + 1];
            }
            lt += __shfl_xor_sync(0xffffffffu, lt, 1);
            lt += __shfl_xor_sync(0xffffffffu, lt, 2);
            l_i[rh] = l_i[rh] * corr + lt;
            m_i[rh] = mn;
#pragma unroll
            for (int a = 0; a < 8; a++) {
                oa[a][s0] *= corr;
                oa[a][s0 + 1] *= corr;
            }
        }

        // ---- O += P V ----
#pragma unroll
        for (int kk = 0; kk < 4; kk++) {
            uint32_t pa0 = h2u(__floats2half2_rn(sa[2 * kk][0], sa[2 * kk][1]));
            uint32_t pa1 = h2u(__floats2half2_rn(sa[2 * kk][2], sa[2 * kk][3]));
            uint32_t pa2 = h2u(__floats2half2_rn(sa[2 * kk + 1][0], sa[2 * kk + 1][1]));
            uint32_t pa3 = h2u(__floats2half2_rn(sa[2 * kk + 1][2], sa[2 * kk + 1][3]));
            const uint32_t rowaddr = vsb +
                (uint32_t)((kk * 16 + (lane & 15)) * KVSTR) * 2;
#pragma unroll
            for (int a = 0; a < 8; a++) {
                uint32_t b0, b1;
                ldmatrix_x2_trans(b0, b1, rowaddr + a * 16);
                mma_f16(oa[a][0], oa[a][1], oa[a][2], oa[a][3],
                        pa0, pa1, pa2, pa3, b0, b1);
            }
        }
        __syncthreads();
    }

    // ---- write context fp16 [B,S,D] ----
    const int b = bh >> 4;
    const int h = bh & 15;
    const float inv0 = 1.0f / l_i[0];
    const float inv1 = 1.0f / l_i[1];
    const int row0 = q0 + rb + g;
    const int row1 = row0 + 8;
#pragma unroll
    for (int a = 0; a < 8; a++) {
        int d = h * HDIM + a * 8 + 2 * t;
        *(__half2*)&C[((size_t)b * SEQ + row0) * DMODEL + d] =
            __floats2half2_rn(oa[a][0] * inv0, oa[a][1] * inv0);
        *(__half2*)&C[((size_t)b * SEQ + row1) * DMODEL + d] =
            __floats2half2_rn(oa[a][2] * inv1, oa[a][3] * inv1);
    }
}

// ---------------------------------------------------------------------------
// Launch
// ---------------------------------------------------------------------------
extern "C" void kernel_launch(void* const* d_in, const int* in_sizes, int n_in,
                              void* d_out, int out_size)
{
    const float* x  = (const float*)d_in[0];
    const float* Wq = (const float*)d_in[1];
    const float* bq = (const float*)d_in[2];
    const float* Wk = (const float*)d_in[3];
    const float* bk = (const float*)d_in[4];
    const float* Wv = (const float*)d_in[5];
    const float* bv = (const float*)d_in[6];
    const float* Wo = (const float*)d_in[7];
    const float* bo = (const float*)d_in[8];
    float* out = (float*)d_out;

    __half *xh, *Wqh, *Wkh, *Wvh, *Woh, *Qh, *Kh, *Vh, *Ch;
    cudaGetSymbolAddress((void**)&xh, g_xh);
    cudaGetSymbolAddress((void**)&Wqh, g_Wqh);
    cudaGetSymbolAddress((void**)&Wkh, g_Wkh);
    cudaGetSymbolAddress((void**)&Wvh, g_Wvh);
    cudaGetSymbolAddress((void**)&Woh, g_Woh);
    cudaGetSymbolAddress((void**)&Qh, g_Qh);
    cudaGetSymbolAddress((void**)&Kh, g_Kh);
    cudaGetSymbolAddress((void**)&Vh, g_Vh);
    cudaGetSymbolAddress((void**)&Ch, g_Ch);

    static int attr_set = 0;
    if (!attr_set) {
        cudaFuncSetAttribute(attn_h,
                             cudaFuncAttributeMaxDynamicSharedMemorySize,
                             AT_SMEM_BYTES);
        cudaFuncSetAttribute(gemm_h,
                             cudaFuncAttributeMaxDynamicSharedMemorySize,
                             GSM_BYTES);
        attr_set = 1;
    }

    cvt_all<<<(TOT4 + 255) / 256, 256>>>(x, Wq, Wk, Wv, Wo,
                                         xh, Wqh, Wkh, Wvh, Woh);

    dim3 gq(DMODEL / TBN, MROWS / TBM, 3);  // fused QKV
    gemm_h<<<gq, 256, GSM_BYTES>>>(xh, Wqh, Wkh, Wvh, bq, bk, bv,
                                   nullptr, Qh, Kh, Vh, 1);

    dim3 agrid(SEQ / 128, BH);
    attn_h<<<agrid, 256, AT_SMEM_BYTES>>>(Qh, Kh, Vh, Ch);

    dim3 go(DMODEL / TBN, MROWS / TBM, 1);
    gemm_h<<<go, 256, GSM_BYTES>>>(Ch, Woh, nullptr, nullptr, bo, nullptr, nullptr,
                                   out, nullptr, nullptr, nullptr, 0);
}

// round 7
// speedup vs baseline: 6.1010x; 1.0516x over previous
#include <cuda_runtime.h>
#include <cuda_fp16.h>
#include <math.h>
#include <cstdint>

// Problem constants
#define BATCH 2
#define SEQ 2048
#define DMODEL 1024
#define NHEADS 16
#define HDIM 64
#define BH (BATCH*NHEADS)          // 32
#define MROWS (BATCH*SEQ)          // 4096

// fp16 scratch (static device arrays -- no allocation allowed)
__device__ __half g_xh[MROWS * DMODEL];
__device__ __half g_Wqh[DMODEL * DMODEL];
__device__ __half g_Wkh[DMODEL * DMODEL];
__device__ __half g_Wvh[DMODEL * DMODEL];
__device__ __half g_Woh[DMODEL * DMODEL];
__device__ __half g_Qh[BH * SEQ * HDIM];   // roped + scaled
__device__ __half g_Kh[BH * SEQ * HDIM];   // roped
__device__ __half g_Vh[BH * SEQ * HDIM];
__device__ __half g_Ch[MROWS * DMODEL];    // context [B,S,D]

// ===========================================================================
// Helpers
// ===========================================================================
__device__ __forceinline__ void mma_f16(float& d0, float& d1, float& d2, float& d3,
                                        uint32_t a0, uint32_t a1, uint32_t a2, uint32_t a3,
                                        uint32_t b0, uint32_t b1) {
    asm volatile(
        "mma.sync.aligned.m16n8k16.row.col.f32.f16.f16.f32 "
        "{%0,%1,%2,%3}, {%4,%5,%6,%7}, {%8,%9}, {%0,%1,%2,%3};"
        : "+f"(d0), "+f"(d1), "+f"(d2), "+f"(d3)
        : "r"(a0), "r"(a1), "r"(a2), "r"(a3), "r"(b0), "r"(b1));
}

__device__ __forceinline__ void ldmatrix_x4(uint32_t& r0, uint32_t& r1,
                                            uint32_t& r2, uint32_t& r3,
                                            uint32_t addr) {
    asm volatile("ldmatrix.sync.aligned.m8n8.x4.shared.b16 {%0,%1,%2,%3}, [%4];"
                 : "=r"(r0), "=r"(r1), "=r"(r2), "=r"(r3) : "r"(addr));
}

__device__ __forceinline__ void ldmatrix_x2_trans(uint32_t& r0, uint32_t& r1,
                                                  uint32_t addr) {
    asm volatile("ldmatrix.sync.aligned.m8n8.x2.trans.shared.b16 {%0,%1}, [%2];"
                 : "=r"(r0), "=r"(r1) : "r"(addr));
}

__device__ __forceinline__ void cp_async16(uint32_t smem_addr, const void* gmem) {
    asm volatile("cp.async.cg.shared.global [%0], [%1], 16;"
                 :: "r"(smem_addr), "l"(gmem) : "memory");
}
#define CP_ASYNC_COMMIT() asm volatile("cp.async.commit_group;" ::: "memory")
#define CP_ASYNC_WAIT(n)  asm volatile("cp.async.wait_group %0;" :: "n"(n) : "memory")

__device__ __forceinline__ uint32_t smem_u32(const void* p) {
    uint32_t a;
    asm("{ .reg .u64 t; cvta.to.shared.u64 t, %1; cvt.u32.u64 %0, t; }"
        : "=r"(a) : "l"(p));
    return a;
}

__device__ __forceinline__ uint32_t h2u(__half2 h) {
    return *(uint32_t*)&h;
}

// ---------------------------------------------------------------------------
// Fused fp32 -> fp16 conversion for x + all 4 weights (one launch)
// ---------------------------------------------------------------------------
#define XN4 (MROWS * DMODEL / 4)      // 1048576
#define WN4 (DMODEL * DMODEL / 4)     // 262144
#define TOT4 (XN4 + 4 * WN4)          // 2097152

__global__ __launch_bounds__(256) void cvt_all(
    const float* __restrict__ x,
    const float* __restrict__ wq, const float* __restrict__ wk,
    const float* __restrict__ wv, const float* __restrict__ wo,
    __half* __restrict__ xh,
    __half* __restrict__ wqh, __half* __restrict__ wkh,
    __half* __restrict__ wvh, __half* __restrict__ woh)
{
    int i = blockIdx.x * blockDim.x + threadIdx.x;
    if (i >= TOT4) return;
    const float* src;
    __half* dst;
    int off;
    if (i < XN4) {
        src = x; dst = xh; off = i;
    } else {
        int j = i - XN4;
        int w = j >> 18;
        off = j & (WN4 - 1);
        src = (w == 0) ? wq : (w == 1) ? wk : (w == 2) ? wv : wo;
        dst = (w == 0) ? wqh : (w == 1) ? wkh : (w == 2) ? wvh : woh;
    }
    float4 v = *(const float4*)&src[(size_t)off * 4];
    *(__half2*)&dst[(size_t)off * 4] = __floats2half2_rn(v.x, v.y);
    *(__half2*)&dst[(size_t)off * 4 + 2] = __floats2half2_rn(v.z, v.w);
}

// ===========================================================================
// fp16 mma GEMM, 4-stage cp.async pipeline, one barrier per BK chunk.
// CTA 128x128, BK=32 halves, 8 warps (2M x 4N), warp tile 64x32, ldmatrix.x4.
// ===========================================================================
#define TBM 128
#define TBN 128
#define TBK 32
#define NCH (DMODEL / TBK)        // 32
#define HSTR 40                   // halves per smem row (80B)
#define STAGE_H (TBM * HSTR)      // halves per matrix per stage
#define GSTAGES 4
#define GSM_BYTES (GSTAGES * 2 * STAGE_H * 2)   // 81920 B

__global__ __launch_bounds__(256)
void gemm_h(const __half* __restrict__ A,
            const __half* __restrict__ W0, const __half* __restrict__ W1,
            const __half* __restrict__ W2,
            const float* __restrict__ b0p, const float* __restrict__ b1p,
            const float* __restrict__ b2p,
            float* __restrict__ outf,
            __half* __restrict__ o0, __half* __restrict__ o1,
            __half* __restrict__ o2,
            int fused)
{
    extern __shared__ __align__(16) __half smh[];
    const uint32_t sb = smem_u32(smh);

    const int z = fused ? blockIdx.z : 0;
    const int mode = fused ? (z + 1) : 0;
    const __half* W = (z == 0) ? W0 : (z == 1) ? W1 : W2;
    const float* bias = (z == 0) ? b0p : (z == 1) ? b1p : b2p;
    __half* outh = (z == 0) ? o0 : (z == 1) ? o1 : o2;

    const int tid = threadIdx.x;
    const int wid = tid >> 5;
    const int lane = tid & 31;
    const int wm = wid & 1;
    const int wn = wid >> 1;
    const int g = lane >> 2;
    const int t = lane & 3;

    const int row0 = blockIdx.y * TBM;
    const int col0 = blockIdx.x * TBN;

    // loader: row = tid>>1, 2x16B at (tid&1)*32B
    const int lrow = tid >> 1;
    const int lhf = (tid & 1) * 16;
    const uint32_t lsoff = (uint32_t)(lrow * HSTR + lhf) * 2;
    const __half* aGrow = &A[(size_t)(row0 + lrow) * DMODEL + lhf];
    const __half* bGrow = &W[(size_t)(col0 + lrow) * DMODEL + lhf];

    const int lr8 = lane & 7;
    const int lg8 = (lane >> 3) & 1;
    const int lk8 = (lane >> 4) & 1;

    float acc[4][4][4];
#pragma unroll
    for (int i = 0; i < 4; i++)
#pragma unroll
        for (int j = 0; j < 4; j++)
#pragma unroll
            for (int r = 0; r < 4; r++) acc[i][j][r] = 0.f;

    // prologue: stages 0..2
#pragma unroll
    for (int p = 0; p < GSTAGES - 1; p++) {
        uint32_t abase = sb + (uint32_t)(p * 2 * STAGE_H) * 2;
        uint32_t bbase = abase + (uint32_t)STAGE_H * 2;
        const int k0 = p * TBK;
        cp_async16(abase + lsoff, aGrow + k0);
        cp_async16(abase + lsoff + 16, aGrow + k0 + 8);
        cp_async16(bbase + lsoff, bGrow + k0);
        cp_async16(bbase + lsoff + 16, bGrow + k0 + 8);
        CP_ASYNC_COMMIT();
    }

    for (int c = 0; c < NCH; c++) {
        CP_ASYNC_WAIT(GSTAGES - 2);   // stage c copies (this thread) done
        __syncthreads();              // visibility + protects stage (c-1)%4

        if (c + GSTAGES - 1 < NCH) {
            const int st = (c + GSTAGES - 1) & (GSTAGES - 1);
            uint32_t abase = sb + (uint32_t)(st * 2 * STAGE_H) * 2;
            uint32_t bbase = abase + (uint32_t)STAGE_H * 2;
            const int k0 = (c + GSTAGES - 1) * TBK;
            cp_async16(abase + lsoff, aGrow + k0);
            cp_async16(abase + lsoff + 16, aGrow + k0 + 8);
            cp_async16(bbase + lsoff, bGrow + k0);
            cp_async16(bbase + lsoff + 16, bGrow + k0 + 8);
        }
        CP_ASYNC_COMMIT();            // empty group in tail keeps counts exact

        const uint32_t asb = sb + (uint32_t)((c & (GSTAGES - 1)) * 2 * STAGE_H) * 2;
        const uint32_t bsb = asb + (uint32_t)STAGE_H * 2;
#pragma unroll
        for (int ks = 0; ks < 2; ks++) {
            const uint32_t acol = (uint32_t)(ks * 16 + lk8 * 8) * 2;
            uint32_t afr[4][4];
#pragma unroll
            for (int am = 0; am < 4; am++) {
                int r = wm * 64 + am * 16 + lr8 + lg8 * 8;
                ldmatrix_x4(afr[am][0], afr[am][1], afr[am][2], afr[am][3],
                            asb + (uint32_t)(r * HSTR) * 2 + acol);
            }
            uint32_t bfr[4][2];
#pragma unroll
            for (int bnp = 0; bnp < 2; bnp++) {
                int n = wn * 32 + bnp * 16 + lr8 + lg8 * 8;
                ldmatrix_x4(bfr[2 * bnp][0], bfr[2 * bnp + 1][0],
                            bfr[2 * bnp][1], bfr[2 * bnp + 1][1],
                            bsb + (uint32_t)(n * HSTR) * 2 + acol);
            }
#pragma unroll
            for (int am = 0; am < 4; am++)
#pragma unroll
                for (int bn = 0; bn < 4; bn++)
                    mma_f16(acc[am][bn][0], acc[am][bn][1],
                            acc[am][bn][2], acc[am][bn][3],
                            afr[am][0], afr[am][1], afr[am][2], afr[am][3],
                            bfr[bn][0], bfr[bn][1]);
        }
    }

    // ---- epilogue ----
#pragma unroll
    for (int bn = 0; bn < 4; bn++) {
        const int n0 = col0 + wn * 32 + bn * 8 + 2 * t;
        const float b0 = __ldg(&bias[n0]);
        const float b1 = __ldg(&bias[n0 + 1]);

        float invf = 0.f;
        if (mode == 1 || mode == 2) {
            int pair = (n0 & 63) >> 1;
            invf = powf(10000.0f, -(float)pair / 32.0f);
        }
#pragma unroll
        for (int am = 0; am < 4; am++) {
            const int r0 = row0 + wm * 64 + am * 16 + g;
#pragma unroll
            for (int rh = 0; rh < 2; rh++) {
                const int r = r0 + rh * 8;
                float v0 = acc[am][bn][rh * 2] + b0;
                float v1 = acc[am][bn][rh * 2 + 1] + b1;
                if (mode == 0) {
                    *(float2*)&outf[(size_t)r * DMODEL + n0] = make_float2(v0, v1);
                } else {
                    const int b = r >> 11;
                    const int s = r & (SEQ - 1);
                    const int h = n0 >> 6;
                    const int d = n0 & 63;
                    if (mode != 3) {
                        float sn, cs;
                        sincosf((float)s * invf, &sn, &cs);
                        float oe = v0 * cs - v1 * sn;
                        float oo = v0 * sn + v1 * cs;
                        if (mode == 1) { oe *= 0.125f; oo *= 0.125f; }
                        v0 = oe; v1 = oo;
                    }
                    __half2 hv = __floats2half2_rn(v0, v1);
                    *(__half2*)&outh[(((size_t)(b * NHEADS + h)) * SEQ + s) * HDIM + d] = hv;
                }
            }
        }
    }
}

// ===========================================================================
// fp16 flash attention, 3-stage KV ring, one barrier per k-tile.
// CTA = (bh, 128-row q tile), 8 warps; warp w owns q rows w*16..+15.
// ===========================================================================
#define KVSTR 72
#define KV_TILE_H (64 * KVSTR)                // halves per K (or V) tile
#define ASTAGES 3
#define AT_SMEM_BYTES (ASTAGES * 2 * KV_TILE_H * 2)   // 55296 B

__global__ __launch_bounds__(256)
void attn_h(const __half* __restrict__ Q,
            const __half* __restrict__ K,
            const __half* __restrict__ V,
            __half* __restrict__ C)
{
    extern __shared__ __align__(16) __half smh[];
    const uint32_t sb = smem_u32(smh);

    const int bh = blockIdx.y;
    const int qt = gridDim.x - 1 - blockIdx.x;   // heavy tiles first
    const int q0 = qt * 128;
    const int tid = threadIdx.x;
    const int wid = tid >> 5;
    const int lane = tid & 31;
    const int g = lane >> 2;
    const int t = lane & 3;
    const int rb = wid * 16;

    const int lr8 = lane & 7;
    const int lg8 = (lane >> 3) & 1;
    const int lk8 = (lane >> 4) & 1;

    const __half* Qb = Q + (((size_t)bh * SEQ) + q0) * HDIM;
    const __half* Kh = K + ((size_t)bh * SEQ) * HDIM;
    const __half* Vh = V + ((size_t)bh * SEQ) * HDIM;

    // Q fragments straight from gmem (pre-roped, pre-scaled)
    uint32_t qfr[4][4];
#pragma unroll
    for (int ks = 0; ks < 4; ks++) {
        const int d0 = ks * 16;
        qfr[ks][0] = *(const uint32_t*)&Qb[(rb + g) * HDIM + d0 + 2 * t];
        qfr[ks][1] = *(const uint32_t*)&Qb[(rb + g + 8) * HDIM + d0 + 2 * t];
        qfr[ks][2] = *(const uint32_t*)&Qb[(rb + g) * HDIM + d0 + 2 * t + 8];
        qfr[ks][3] = *(const uint32_t*)&Qb[(rb + g + 8) * HDIM + d0 + 2 * t + 8];
    }

    float oa[8][4];
#pragma unroll
    for (int a = 0; a < 8; a++)
#pragma unroll
        for (int r = 0; r < 4; r++) oa[a][r] = 0.f;
    float m_i[2] = {-INFINITY, -INFINITY};
    float l_i[2] = {0.f, 0.f};

    const int nkt = (q0 + 128) >> 6;

    const int lrow = tid >> 2;
    const int lhf = (tid & 3) * 16;
    const uint32_t lsoff = (uint32_t)(lrow * KVSTR + lhf) * 2;

    // prologue: tiles 0 and 1 (nkt >= 2 always)
#pragma unroll
    for (int p = 0; p < ASTAGES - 1; p++) {
        uint32_t kb = sb + (uint32_t)(p * 2 * KV_TILE_H) * 2;
        uint32_t vb = kb + (uint32_t)KV_TILE_H * 2;
        const size_t r = (size_t)(p * 64 + lrow) * HDIM + lhf;
        cp_async16(kb + lsoff, &Kh[r]);
        cp_async16(kb + lsoff + 16, &Kh[r + 8]);
        cp_async16(vb + lsoff, &Vh[r]);
        cp_async16(vb + lsoff + 16, &Vh[r + 8]);
        CP_ASYNC_COMMIT();
    }

    int stc = 0;                                  // stage of tile kt
    for (int kt = 0; kt < nkt; kt++) {
        CP_ASYNC_WAIT(ASTAGES - 2);
        __syncthreads();

        if (kt + ASTAGES - 1 < nkt) {
            int stn = stc + (ASTAGES - 1);
            if (stn >= ASTAGES) stn -= ASTAGES;
            uint32_t kb = sb + (uint32_t)(stn * 2 * KV_TILE_H) * 2;
            uint32_t vb = kb + (uint32_t)KV_TILE_H * 2;
            const size_t r = (size_t)((kt + ASTAGES - 1) * 64 + lrow) * HDIM + lhf;
            cp_async16(kb + lsoff, &Kh[r]);
            cp_async16(kb + lsoff + 16, &Kh[r + 8]);
            cp_async16(vb + lsoff, &Vh[r]);
            cp_async16(vb + lsoff + 16, &Vh[r + 8]);
        }
        CP_ASYNC_COMMIT();

        const uint32_t ksb = sb + (uint32_t)(stc * 2 * KV_TILE_H) * 2;
        const uint32_t vsb = ksb + (uint32_t)KV_TILE_H * 2;
        const int k0g = kt * 64;

        // ---- S = Q K^T ----
        float sa[8][4];
#pragma unroll
        for (int a = 0; a < 8; a++)
#pragma unroll
            for (int r = 0; r < 4; r++) sa[a][r] = 0.f;

#pragma unroll
        for (int ks = 0; ks < 4; ks++) {
            const uint32_t kcol = (uint32_t)(ks * 16 + lk8 * 8) * 2;
            uint32_t bk[8][2];
#pragma unroll
            for (int ap = 0; ap < 4; ap++) {
                int n = ap * 16 + lr8 + lg8 * 8;
                ldmatrix_x4(bk[2 * ap][0], bk[2 * ap + 1][0],
                            bk[2 * ap][1], bk[2 * ap + 1][1],
                            ksb + (uint32_t)(n * KVSTR) * 2 + kcol);
            }
#pragma unroll
            for (int a = 0; a < 8; a++)
                mma_f16(sa[a][0], sa[a][1], sa[a][2], sa[a][3],
                        qfr[ks][0], qfr[ks][1], qfr[ks][2], qfr[ks][3],
                        bk[a][0], bk[a][1]);
        }

        // ---- causal mask ----
        if (k0g + 63 > q0 + rb) {
            const int r0g = q0 + rb + g;
            const int r1g = r0g + 8;
#pragma unroll
            for (int a = 0; a < 8; a++) {
                int c0 = k0g + a * 8 + 2 * t;
                int c1 = c0 + 1;
                if (c0 > r0g) sa[a][0] = -INFINITY;
                if (c1 > r0g) sa[a][1] = -INFINITY;
                if (c0 > r1g) sa[a][2] = -INFINITY;
                if (c1 > r1g) sa[a][3] = -INFINITY;
            }
        }

        // ---- online softmax ----
#pragma unroll
        for (int rh = 0; rh < 2; rh++) {
            const int s0 = rh * 2;
            float mt = -INFINITY;
#pragma unroll
            for (int a = 0; a < 8; a++)
                mt = fmaxf(mt, fmaxf(sa[a][s0], sa[a][s0 + 1]));
            mt = fmaxf(mt, __shfl_xor_sync(0xffffffffu, mt, 1));
            mt = fmaxf(mt, __shfl_xor_sync(0xffffffffu, mt, 2));
            float mn = fmaxf(m_i[rh], mt);
            float corr = __expf(m_i[rh] - mn);
            float lt = 0.f;
#pragma unroll
            for (int a = 0; a < 8; a++) {
                sa[a][s0] = __expf(sa[a][s0] - mn);
                sa[a][s0 + 1] = __expf(sa[a][s0 + 1] - mn);
                lt += sa[a][s0] + sa[a][s0 + 1];
            }
            lt += __shfl_xor_sync(0xffffffffu, lt, 1);
            lt += __shfl_xor_sync(0xffffffffu, lt, 2);
            l_i[rh] = l_i[rh] * corr + lt;
            m_i[rh] = mn;
#pragma unroll
            for (int a = 0; a < 8; a++) {
                oa[a][s0] *= corr;
                oa[a][s0 + 1] *= corr;
            }
        }

        // ---- O += P V ----
#pragma unroll
        for (int kk = 0; kk < 4; kk++) {
            uint32_t pa0 = h2u(__floats2half2_rn(sa[2 * kk][0], sa[2 * kk][1]));
            uint32_t pa1 = h2u(__floats2half2_rn(sa[2 * kk][2], sa[2 * kk][3]));
            uint32_t pa2 = h2u(__floats2half2_rn(sa[2 * kk + 1][0], sa[2 * kk + 1][1]));
            uint32_t pa3 = h2u(__floats2half2_rn(sa[2 * kk + 1][2], sa[2 * kk + 1][3]));
            const uint32_t rowaddr = vsb +
                (uint32_t)((kk * 16 + (lane & 15)) * KVSTR) * 2;
#pragma unroll
            for (int a = 0; a < 8; a++) {
                uint32_t b0, b1;
                ldmatrix_x2_trans(b0, b1, rowaddr + a * 16);
                mma_f16(oa[a][0], oa[a][1], oa[a][2], oa[a][3],
                        pa0, pa1, pa2, pa3, b0, b1);
            }
        }

        if (++stc == ASTAGES) stc = 0;
    }

    // ---- write context fp16 [B,S,D] ----
    const int b = bh >> 4;
    const int h = bh & 15;
    const float inv0 = 1.0f / l_i[0];
    const float inv1 = 1.0f / l_i[1];
    const int row0 = q0 + rb + g;
    const int row1 = row0 + 8;
#pragma unroll
    for (int a = 0; a < 8; a++) {
        int d = h * HDIM + a * 8 + 2 * t;
        *(__half2*)&C[((size_t)b * SEQ + row0) * DMODEL + d] =
            __floats2half2_rn(oa[a][0] * inv0, oa[a][1] * inv0);
        *(__half2*)&C[((size_t)b * SEQ + row1) * DMODEL + d] =
            __floats2half2_rn(oa[a][2] * inv1, oa[a][3] * inv1);
    }
}

// ---------------------------------------------------------------------------
// Launch
// ---------------------------------------------------------------------------
extern "C" void kernel_launch(void* const* d_in, const int* in_sizes, int n_in,
                              void* d_out, int out_size)
{
    const float* x  = (const float*)d_in[0];
    const float* Wq = (const float*)d_in[1];
    const float* bq = (const float*)d_in[2];
    const float* Wk = (const float*)d_in[3];
    const float* bk = (const float*)d_in[4];
    const float* Wv = (const float*)d_in[5];
    const float* bv = (const float*)d_in[6];
    const float* Wo = (const float*)d_in[7];
    const float* bo = (const float*)d_in[8];
    float* out = (float*)d_out;

    __half *xh, *Wqh, *Wkh, *Wvh, *Woh, *Qh, *Kh, *Vh, *Ch;
    cudaGetSymbolAddress((void**)&xh, g_xh);
    cudaGetSymbolAddress((void**)&Wqh, g_Wqh);
    cudaGetSymbolAddress((void**)&Wkh, g_Wkh);
    cudaGetSymbolAddress((void**)&Wvh, g_Wvh);
    cudaGetSymbolAddress((void**)&Woh, g_Woh);
    cudaGetSymbolAddress((void**)&Qh, g_Qh);
    cudaGetSymbolAddress((void**)&Kh, g_Kh);
    cudaGetSymbolAddress((void**)&Vh, g_Vh);
    cudaGetSymbolAddress((void**)&Ch, g_Ch);

    static int attr_set = 0;
    if (!attr_set) {
        cudaFuncSetAttribute(attn_h,
                             cudaFuncAttributeMaxDynamicSharedMemorySize,
                             AT_SMEM_BYTES);
        cudaFuncSetAttribute(gemm_h,
                             cudaFuncAttributeMaxDynamicSharedMemorySize,
                             GSM_BYTES);
        attr_set = 1;
    }

    cvt_all<<<(TOT4 + 255) / 256, 256>>>(x, Wq, Wk, Wv, Wo,
                                         xh, Wqh, Wkh, Wvh, Woh);

    dim3 gq(DMODEL / TBN, MROWS / TBM, 3);  // fused QKV
    gemm_h<<<gq, 256, GSM_BYTES>>>(xh, Wqh, Wkh, Wvh, bq, bk, bv,
                                   nullptr, Qh, Kh, Vh, 1);

    dim3 agrid(SEQ / 128, BH);
    attn_h<<<agrid, 256, AT_SMEM_BYTES>>>(Qh, Kh, Vh, Ch);

    dim3 go(DMODEL / TBN, MROWS / TBM, 1);
    gemm_h<<<go, 256, GSM_BYTES>>>(Ch, Woh, nullptr, nullptr, bo, nullptr, nullptr,
                                   out, nullptr, nullptr, nullptr, 0);
}

// round 8
// speedup vs baseline: 6.3324x; 1.0379x over previous
#include <cuda_runtime.h>
#include <cuda_fp16.h>
#include <math.h>
#include <cstdint>

// Problem constants
#define BATCH 2
#define SEQ 2048
#define DMODEL 1024
#define NHEADS 16
#define HDIM 64
#define BH (BATCH*NHEADS)          // 32
#define MROWS (BATCH*SEQ)          // 4096

// fp16 scratch (static device arrays -- no allocation allowed)
__device__ __half g_xh[MROWS * DMODEL];
__device__ __half g_Wqh[DMODEL * DMODEL];
__device__ __half g_Wkh[DMODEL * DMODEL];
__device__ __half g_Wvh[DMODEL * DMODEL];
__device__ __half g_Woh[DMODEL * DMODEL];
__device__ __half g_Qh[BH * SEQ * HDIM];   // roped + scaled
__device__ __half g_Kh[BH * SEQ * HDIM];   // roped
__device__ __half g_Vh[BH * SEQ * HDIM];
__device__ __half g_Ch[MROWS * DMODEL];    // context [B,S,D]

// ===========================================================================
// Helpers
// ===========================================================================
__device__ __forceinline__ void mma_f16(float& d0, float& d1, float& d2, float& d3,
                                        uint32_t a0, uint32_t a1, uint32_t a2, uint32_t a3,
                                        uint32_t b0, uint32_t b1) {
    asm volatile(
        "mma.sync.aligned.m16n8k16.row.col.f32.f16.f16.f32 "
        "{%0,%1,%2,%3}, {%4,%5,%6,%7}, {%8,%9}, {%0,%1,%2,%3};"
        : "+f"(d0), "+f"(d1), "+f"(d2), "+f"(d3)
        : "r"(a0), "r"(a1), "r"(a2), "r"(a3), "r"(b0), "r"(b1));
}

__device__ __forceinline__ void ldmatrix_x4(uint32_t& r0, uint32_t& r1,
                                            uint32_t& r2, uint32_t& r3,
                                            uint32_t addr) {
    asm volatile("ldmatrix.sync.aligned.m8n8.x4.shared.b16 {%0,%1,%2,%3}, [%4];"
                 : "=r"(r0), "=r"(r1), "=r"(r2), "=r"(r3) : "r"(addr));
}

__device__ __forceinline__ void ldmatrix_x2_trans(uint32_t& r0, uint32_t& r1,
                                                  uint32_t addr) {
    asm volatile("ldmatrix.sync.aligned.m8n8.x2.trans.shared.b16 {%0,%1}, [%2];"
                 : "=r"(r0), "=r"(r1) : "r"(addr));
}

__device__ __forceinline__ void cp_async16(uint32_t smem_addr, const void* gmem) {
    asm volatile("cp.async.cg.shared.global [%0], [%1], 16;"
                 :: "r"(smem_addr), "l"(gmem) : "memory");
}
#define CP_ASYNC_COMMIT() asm volatile("cp.async.commit_group;" ::: "memory")
#define CP_ASYNC_WAIT(n)  asm volatile("cp.async.wait_group %0;" :: "n"(n) : "memory")

__device__ __forceinline__ uint32_t smem_u32(const void* p) {
    uint32_t a;
    asm("{ .reg .u64 t; cvta.to.shared.u64 t, %1; cvt.u32.u64 %0, t; }"
        : "=r"(a) : "l"(p));
    return a;
}

__device__ __forceinline__ uint32_t h2u(__half2 h) {
    return *(uint32_t*)&h;
}

// ---------------------------------------------------------------------------
// Fused fp32 -> fp16 conversion: each thread converts 4 float4 (64B) -> MLP 4
// ---------------------------------------------------------------------------
#define XN4 (MROWS * DMODEL / 4)      // 1048576
#define WN4 (DMODEL * DMODEL / 4)     // 262144
#define TOT4 (XN4 + 4 * WN4)          // 2097152
#define CVT_THREADS (TOT4 / 4)        // 524288

__global__ __launch_bounds__(256) void cvt_all(
    const float* __restrict__ x,
    const float* __restrict__ wq, const float* __restrict__ wk,
    const float* __restrict__ wv, const float* __restrict__ wo,
    __half* __restrict__ xh,
    __half* __restrict__ wqh, __half* __restrict__ wkh,
    __half* __restrict__ wvh, __half* __restrict__ woh)
{
    int i = blockIdx.x * blockDim.x + threadIdx.x;
    if (i >= CVT_THREADS) return;
    int e0 = i * 4;   // first float4 index; group of 4 never crosses a tensor
    const float* src;
    __half* dst;
    int off;
    if (e0 < XN4) {
        src = x; dst = xh; off = e0;
    } else {
        int j = e0 - XN4;
        int w = j >> 18;
        off = j & (WN4 - 1);
        src = (w == 0) ? wq : (w == 1) ? wk : (w == 2) ? wv : wo;
        dst = (w == 0) ? wqh : (w == 1) ? wkh : (w == 2) ? wvh : wo == src ? woh : woh;
    }
#pragma unroll
    for (int u = 0; u < 4; u++) {
        float4 v = *(const float4*)&src[(size_t)(off + u) * 4];
        *(__half2*)&dst[(size_t)(off + u) * 4] = __floats2half2_rn(v.x, v.y);
        *(__half2*)&dst[(size_t)(off + u) * 4 + 2] = __floats2half2_rn(v.z, v.w);
    }
}

// ===========================================================================
// fp16 mma GEMM, 4-stage cp.async pipeline, occupancy-oriented:
// CTA tile 128x64 (M x N), 8 warps = 4M x 2N, warp tile 32x32, BK=32 halves.
// 3 CTAs/SM (smem 61.4KB/CTA, regs capped ~85).
// smem stage = 192 rows x HSTR (A rows 0-127, B rows 128-191).
// ===========================================================================
#define TBM 128
#define TBN 64
#define TBK 32
#define NCH (DMODEL / TBK)        // 32
#define HSTR 40                   // halves per smem row (80B)
#define STAGE_ROWS (TBM + TBN)    // 192
#define STAGE_H (STAGE_ROWS * HSTR)   // 7680 halves
#define GSTAGES 4
#define GSM_BYTES (GSTAGES * STAGE_H * 2)   // 61440 B

__global__ __launch_bounds__(256, 3)
void gemm_h(const __half* __restrict__ A,
            const __half* __restrict__ W0, const __half* __restrict__ W1,
            const __half* __restrict__ W2,
            const float* __restrict__ b0p, const float* __restrict__ b1p,
            const float* __restrict__ b2p,
            float* __restrict__ outf,
            __half* __restrict__ o0, __half* __restrict__ o1,
            __half* __restrict__ o2,
            int fused)
{
    extern __shared__ __align__(16) __half smh[];
    const uint32_t sb = smem_u32(smh);

    const int z = fused ? blockIdx.z : 0;
    const int mode = fused ? (z + 1) : 0;
    const __half* W = (z == 0) ? W0 : (z == 1) ? W1 : W2;
    const float* bias = (z == 0) ? b0p : (z == 1) ? b1p : b2p;
    __half* outh = (z == 0) ? o0 : (z == 1) ? o1 : o2;

    const int tid = threadIdx.x;
    const int wid = tid >> 5;
    const int lane = tid & 31;
    const int wm = wid & 3;        // 4 over M (32 rows each)
    const int wn = wid >> 2;       // 2 over N (32 cols each)
    const int g = lane >> 2;
    const int t = lane & 3;

    const int row0 = blockIdx.y * TBM;
    const int col0 = blockIdx.x * TBN;

    // loader: 768 16B-chunks per stage; thread does chunks tid, tid+256, tid+512
    // chunk c: row = c>>2 (A rows [0,128), B rows [128,192)), off = (c&3)*8 halves
    const int r0l = tid >> 2;                  // A row (j=0): 0..63
    const int off_h = (tid & 3) * 8;           // halves
    const uint32_t ls0 = (uint32_t)(r0l * HSTR + off_h) * 2;
    const uint32_t ls1 = (uint32_t)((r0l + 64) * HSTR + off_h) * 2;
    const uint32_t ls2 = (uint32_t)((r0l + 128) * HSTR + off_h) * 2;
    const __half* g0 = &A[(size_t)(row0 + r0l) * DMODEL + off_h];
    const __half* g1 = &A[(size_t)(row0 + r0l + 64) * DMODEL + off_h];
    const __half* g2 = &W[(size_t)(col0 + r0l) * DMODEL + off_h];

    const int lr8 = lane & 7;
    const int lg8 = (lane >> 3) & 1;
    const int lk8 = (lane >> 4) & 1;

    float acc[2][4][4];
#pragma unroll
    for (int i = 0; i < 2; i++)
#pragma unroll
        for (int j = 0; j < 4; j++)
#pragma unroll
            for (int r = 0; r < 4; r++) acc[i][j][r] = 0.f;

    // prologue: stages 0..2
#pragma unroll
    for (int p = 0; p < GSTAGES - 1; p++) {
        uint32_t stb = sb + (uint32_t)(p * STAGE_H) * 2;
        const int k0 = p * TBK;
        cp_async16(stb + ls0, g0 + k0);
        cp_async16(stb + ls1, g1 + k0);
        cp_async16(stb + ls2, g2 + k0);
        CP_ASYNC_COMMIT();
    }

    for (int c = 0; c < NCH; c++) {
        CP_ASYNC_WAIT(GSTAGES - 2);
        __syncthreads();

        if (c + GSTAGES - 1 < NCH) {
            const int st = (c + GSTAGES - 1) & (GSTAGES - 1);
            uint32_t stb = sb + (uint32_t)(st * STAGE_H) * 2;
            const int k0 = (c + GSTAGES - 1) * TBK;
            cp_async16(stb + ls0, g0 + k0);
            cp_async16(stb + ls1, g1 + k0);
            cp_async16(stb + ls2, g2 + k0);
        }
        CP_ASYNC_COMMIT();

        const uint32_t stb = sb + (uint32_t)((c & (GSTAGES - 1)) * STAGE_H) * 2;
#pragma unroll
        for (int ks = 0; ks < 2; ks++) {
            const uint32_t acol = (uint32_t)(ks * 16 + lk8 * 8) * 2;
            uint32_t afr[2][4];
#pragma unroll
            for (int am = 0; am < 2; am++) {
                int r = wm * 32 + am * 16 + lr8 + lg8 * 8;
                ldmatrix_x4(afr[am][0], afr[am][1], afr[am][2], afr[am][3],
                            stb + (uint32_t)(r * HSTR) * 2 + acol);
            }
            uint32_t bfr[4][2];
#pragma unroll
            for (int bnp = 0; bnp < 2; bnp++) {
                int n = wn * 32 + bnp * 16 + lr8 + lg8 * 8;
                ldmatrix_x4(bfr[2 * bnp][0], bfr[2 * bnp + 1][0],
                            bfr[2 * bnp][1], bfr[2 * bnp + 1][1],
                            stb + (uint32_t)((128 + n) * HSTR) * 2 + acol);
            }
#pragma unroll
            for (int am = 0; am < 2; am++)
#pragma unroll
                for (int bn = 0; bn < 4; bn++)
                    mma_f16(acc[am][bn][0], acc[am][bn][1],
                            acc[am][bn][2], acc[am][bn][3],
                            afr[am][0], afr[am][1], afr[am][2], afr[am][3],
                            bfr[bn][0], bfr[bn][1]);
        }
    }

    // ---- epilogue ----
#pragma unroll
    for (int bn = 0; bn < 4; bn++) {
        const int n0 = col0 + wn * 32 + bn * 8 + 2 * t;
        const float b0 = __ldg(&bias[n0]);
        const float b1 = __ldg(&bias[n0 + 1]);

        float invf = 0.f;
        if (mode == 1 || mode == 2) {
            int pair = (n0 & 63) >> 1;
            invf = powf(10000.0f, -(float)pair / 32.0f);
        }
#pragma unroll
        for (int am = 0; am < 2; am++) {
            const int r0 = row0 + wm * 32 + am * 16 + g;
#pragma unroll
            for (int rh = 0; rh < 2; rh++) {
                const int r = r0 + rh * 8;
                float v0 = acc[am][bn][rh * 2] + b0;
                float v1 = acc[am][bn][rh * 2 + 1] + b1;
                if (mode == 0) {
                    *(float2*)&outf[(size_t)r * DMODEL + n0] = make_float2(v0, v1);
                } else {
                    const int b = r >> 11;
                    const int s = r & (SEQ - 1);
                    const int h = n0 >> 6;
                    const int d = n0 & 63;
                    if (mode != 3) {
                        float sn, cs;
                        sincosf((float)s * invf, &sn, &cs);
                        float oe = v0 * cs - v1 * sn;
                        float oo = v0 * sn + v1 * cs;
                        if (mode == 1) { oe *= 0.125f; oo *= 0.125f; }
                        v0 = oe; v1 = oo;
                    }
                    __half2 hv = __floats2half2_rn(v0, v1);
                    *(__half2*)&outh[(((size_t)(b * NHEADS + h)) * SEQ + s) * HDIM + d] = hv;
                }
            }
        }
    }
}

// ===========================================================================
// fp16 flash attention, 3-stage KV ring, one barrier per k-tile.
// CTA = (bh, 128-row q tile), 8 warps; warp w owns q rows w*16..+15.
// ===========================================================================
#define KVSTR 72
#define KV_TILE_H (64 * KVSTR)
#define ASTAGES 3
#define AT_SMEM_BYTES (ASTAGES * 2 * KV_TILE_H * 2)   // 55296 B

__global__ __launch_bounds__(256)
void attn_h(const __half* __restrict__ Q,
            const __half* __restrict__ K,
            const __half* __restrict__ V,
            __half* __restrict__ C)
{
    extern __shared__ __align__(16) __half smh[];
    const uint32_t sb = smem_u32(smh);

    const int bh = blockIdx.y;
    const int qt = gridDim.x - 1 - blockIdx.x;   // heavy tiles first
    const int q0 = qt * 128;
    const int tid = threadIdx.x;
    const int wid = tid >> 5;
    const int lane = tid & 31;
    const int g = lane >> 2;
    const int t = lane & 3;
    const int rb = wid * 16;

    const int lr8 = lane & 7;
    const int lg8 = (lane >> 3) & 1;
    const int lk8 = (lane >> 4) & 1;

    const __half* Qb = Q + (((size_t)bh * SEQ) + q0) * HDIM;
    const __half* Kh = K + ((size_t)bh * SEQ) * HDIM;
    const __half* Vh = V + ((size_t)bh * SEQ) * HDIM;

    // Q fragments straight from gmem (pre-roped, pre-scaled)
    uint32_t qfr[4][4];
#pragma unroll
    for (int ks = 0; ks < 4; ks++) {
        const int d0 = ks * 16;
        qfr[ks][0] = *(const uint32_t*)&Qb[(rb + g) * HDIM + d0 + 2 * t];
        qfr[ks][1] = *(const uint32_t*)&Qb[(rb + g + 8) * HDIM + d0 + 2 * t];
        qfr[ks][2] = *(const uint32_t*)&Qb[(rb + g) * HDIM + d0 + 2 * t + 8];
        qfr[ks][3] = *(const uint32_t*)&Qb[(rb + g + 8) * HDIM + d0 + 2 * t + 8];
    }

    float oa[8][4];
#pragma unroll
    for (int a = 0; a < 8; a++)
#pragma unroll
        for (int r = 0; r < 4; r++) oa[a][r] = 0.f;
    float m_i[2] = {-INFINITY, -INFINITY};
    float l_i[2] = {0.f, 0.f};

    const int nkt = (q0 + 128) >> 6;

    const int lrow = tid >> 2;
    const int lhf = (tid & 3) * 16;
    const uint32_t lsoff = (uint32_t)(lrow * KVSTR + lhf) * 2;

    // prologue: tiles 0 and 1 (nkt >= 2 always)
#pragma unroll
    for (int p = 0; p < ASTAGES - 1; p++) {
        uint32_t kb = sb + (uint32_t)(p * 2 * KV_TILE_H) * 2;
        uint32_t vb = kb + (uint32_t)KV_TILE_H * 2;
        const size_t r = (size_t)(p * 64 + lrow) * HDIM + lhf;
        cp_async16(kb + lsoff, &Kh[r]);
        cp_async16(kb + lsoff + 16, &Kh[r + 8]);
        cp_async16(vb + lsoff, &Vh[r]);
        cp_async16(vb + lsoff + 16, &Vh[r + 8]);
        CP_ASYNC_COMMIT();
    }

    int stc = 0;
    for (int kt = 0; kt < nkt; kt++) {
        CP_ASYNC_WAIT(ASTAGES - 2);
        __syncthreads();

        if (kt + ASTAGES - 1 < nkt) {
            int stn = stc + (ASTAGES - 1);
            if (stn >= ASTAGES) stn -= ASTAGES;
            uint32_t kb = sb + (uint32_t)(stn * 2 * KV_TILE_H) * 2;
            uint32_t vb = kb + (uint32_t)KV_TILE_H * 2;
            const size_t r = (size_t)((kt + ASTAGES - 1) * 64 + lrow) * HDIM + lhf;
            cp_async16(kb + lsoff, &Kh[r]);
            cp_async16(kb + lsoff + 16, &Kh[r + 8]);
            cp_async16(vb + lsoff, &Vh[r]);
            cp_async16(vb + lsoff + 16, &Vh[r + 8]);
        }
        CP_ASYNC_COMMIT();

        const uint32_t ksb = sb + (uint32_t)(stc * 2 * KV_TILE_H) * 2;
        const uint32_t vsb = ksb + (uint32_t)KV_TILE_H * 2;
        const int k0g = kt * 64;

        // ---- S = Q K^T ----
        float sa[8][4];
#pragma unroll
        for (int a = 0; a < 8; a++)
#pragma unroll
            for (int r = 0; r < 4; r++) sa[a][r] = 0.f;

#pragma unroll
        for (int ks = 0; ks < 4; ks++) {
            const uint32_t kcol = (uint32_t)(ks * 16 + lk8 * 8) * 2;
            uint32_t bk[8][2];
#pragma unroll
            for (int ap = 0; ap < 4; ap++) {
                int n = ap * 16 + lr8 + lg8 * 8;
                ldmatrix_x4(bk[2 * ap][0], bk[2 * ap + 1][0],
                            bk[2 * ap][1], bk[2 * ap + 1][1],
                            ksb + (uint32_t)(n * KVSTR) * 2 + kcol);
            }
#pragma unroll
            for (int a = 0; a < 8; a++)
                mma_f16(sa[a][0], sa[a][1], sa[a][2], sa[a][3],
                        qfr[ks][0], qfr[ks][1], qfr[ks][2], qfr[ks][3],
                        bk[a][0], bk[a][1]);
        }

        // ---- causal mask ----
        if (k0g + 63 > q0 + rb) {
            const int r0g = q0 + rb + g;
            const int r1g = r0g + 8;
#pragma unroll
            for (int a = 0; a < 8; a++) {
                int c0 = k0g + a * 8 + 2 * t;
                int c1 = c0 + 1;
                if (c0 > r0g) sa[a][0] = -INFINITY;
                if (c1 > r0g) sa[a][1] = -INFINITY;
                if (c0 > r1g) sa[a][2] = -INFINITY;
                if (c1 > r1g) sa[a][3] = -INFINITY;
            }
        }

        // ---- online softmax ----
#pragma unroll
        for (int rh = 0; rh < 2; rh++) {
            const int s0 = rh * 2;
            float mt = -INFINITY;
#pragma unroll
            for (int a = 0; a < 8; a++)
                mt = fmaxf(mt, fmaxf(sa[a][s0], sa[a][s0 + 1]));
            mt = fmaxf(mt, __shfl_xor_sync(0xffffffffu, mt, 1));
            mt = fmaxf(mt, __shfl_xor_sync(0xffffffffu, mt, 2));
            float mn = fmaxf(m_i[rh], mt);
            float corr = __expf(m_i[rh] - mn);
            float lt = 0.f;
#pragma unroll
            for (int a = 0; a < 8; a++) {
                sa[a][s0] = __expf(sa[a][s0] - mn);
                sa[a][s0 + 1] = __expf(sa[a][s0 + 1] - mn);
                lt += sa[a][s0] + sa[a][s0 + 1];
            }
            lt += __shfl_xor_sync(0xffffffffu, lt, 1);
            lt += __shfl_xor_sync(0xffffffffu, lt, 2);
            l_i[rh] = l_i[rh] * corr + lt;
            m_i[rh] = mn;
#pragma unroll
            for (int a = 0; a < 8; a++) {
                oa[a][s0] *= corr;
                oa[a][s0 + 1] *= corr;
            }
        }

        // ---- O += P V ----
#pragma unroll
        for (int kk = 0; kk < 4; kk++) {
            uint32_t pa0 = h2u(__floats2half2_rn(sa[2 * kk][0], sa[2 * kk][1]));
            uint32_t pa1 = h2u(__floats2half2_rn(sa[2 * kk][2], sa[2 * kk][3]));
            uint32_t pa2 = h2u(__floats2half2_rn(sa[2 * kk + 1][0], sa[2 * kk + 1][1]));
            uint32_t pa3 = h2u(__floats2half2_rn(sa[2 * kk + 1][2], sa[2 * kk + 1][3]));
            const uint32_t rowaddr = vsb +
                (uint32_t)((kk * 16 + (lane & 15)) * KVSTR) * 2;
#pragma unroll
            for (int a = 0; a < 8; a++) {
                uint32_t b0, b1;
                ldmatrix_x2_trans(b0, b1, rowaddr + a * 16);
                mma_f16(oa[a][0], oa[a][1], oa[a][2], oa[a][3],
                        pa0, pa1, pa2, pa3, b0, b1);
            }
        }

        if (++stc == ASTAGES) stc = 0;
    }

    // ---- write context fp16 [B,S,D] ----
    const int b = bh >> 4;
    const int h = bh & 15;
    const float inv0 = 1.0f / l_i[0];
    const float inv1 = 1.0f / l_i[1];
    const int row0 = q0 + rb + g;
    const int row1 = row0 + 8;
#pragma unroll
    for (int a = 0; a < 8; a++) {
        int d = h * HDIM + a * 8 + 2 * t;
        *(__half2*)&C[((size_t)b * SEQ + row0) * DMODEL + d] =
            __floats2half2_rn(oa[a][0] * inv0, oa[a][1] * inv0);
        *(__half2*)&C[((size_t)b * SEQ + row1) * DMODEL + d] =
            __floats2half2_rn(oa[a][2] * inv1, oa[a][3] * inv1);
    }
}

// ---------------------------------------------------------------------------
// Launch
// ---------------------------------------------------------------------------
extern "C" void kernel_launch(void* const* d_in, const int* in_sizes, int n_in,
                              void* d_out, int out_size)
{
    const float* x  = (const float*)d_in[0];
    const float* Wq = (const float*)d_in[1];
    const float* bq = (const float*)d_in[2];
    const float* Wk = (const float*)d_in[3];
    const float* bk = (const float*)d_in[4];
    const float* Wv = (const float*)d_in[5];
    const float* bv = (const float*)d_in[6];
    const float* Wo = (const float*)d_in[7];
    const float* bo = (const float*)d_in[8];
    float* out = (float*)d_out;

    __half *xh, *Wqh, *Wkh, *Wvh, *Woh, *Qh, *Kh, *Vh, *Ch;
    cudaGetSymbolAddress((void**)&xh, g_xh);
    cudaGetSymbolAddress((void**)&Wqh, g_Wqh);
    cudaGetSymbolAddress((void**)&Wkh, g_Wkh);
    cudaGetSymbolAddress((void**)&Wvh, g_Wvh);
    cudaGetSymbolAddress((void**)&Woh, g_Woh);
    cudaGetSymbolAddress((void**)&Qh, g_Qh);
    cudaGetSymbolAddress((void**)&Kh, g_Kh);
    cudaGetSymbolAddress((void**)&Vh, g_Vh);
    cudaGetSymbolAddress((void**)&Ch, g_Ch);

    static int attr_set = 0;
    if (!attr_set) {
        cudaFuncSetAttribute(attn_h,
                             cudaFuncAttributeMaxDynamicSharedMemorySize,
                             AT_SMEM_BYTES);
        cudaFuncSetAttribute(gemm_h,
                             cudaFuncAttributeMaxDynamicSharedMemorySize,
                             GSM_BYTES);
        attr_set = 1;
    }

    cvt_all<<<(CVT_THREADS + 255) / 256, 256>>>(x, Wq, Wk, Wv, Wo,
                                                xh, Wqh, Wkh, Wvh, Woh);

    dim3 gq(DMODEL / TBN, MROWS / TBM, 3);  // (16, 32, 3) fused QKV
    gemm_h<<<gq, 256, GSM_BYTES>>>(xh, Wqh, Wkh, Wvh, bq, bk, bv,
                                   nullptr, Qh, Kh, Vh, 1);

    dim3 agrid(SEQ / 128, BH);
    attn_h<<<agrid, 256, AT_SMEM_BYTES>>>(Qh, Kh, Vh, Ch);

    dim3 go(DMODEL / TBN, MROWS / TBM, 1);  // (16, 32)
    gemm_h<<<go, 256, GSM_BYTES>>>(Ch, Woh, nullptr, nullptr, bo, nullptr, nullptr,
                                   out, nullptr, nullptr, nullptr, 0);
}